// round 12
// baseline (speedup 1.0000x reference)
#include <cuda_runtime.h>
#include <cuda_bf16.h>
#include <cuda_fp16.h>
#include <cstdint>
#include <math.h>

#define BT 4096
#define TT 2048
#define DD 512
#define SS 256
#define LLAYERS 4
#define DFFN 1368
#define VV 32000

#if defined(__CUDA_ARCH__) && defined(__CUDA_ARCH_FEAT_SM103_ALL)
#define HAS_TCG 1
#else
#define HAS_TCG 0
#endif

typedef __nv_bfloat16 bf16;

// ---------------- scratch ----------------
__device__ float g_h[BT * DD];
__device__ __align__(16) bf16 g_xnh[BT * DD];   // bf16 pairs (layers) or fp16 bits (final LN)
__device__ __align__(16) bf16 g_xnl[BT * DD];
__device__ float g_bu[BT * SS];
__device__ __align__(16) bf16 g_buh[BT * SS];
__device__ __align__(16) bf16 g_bul[BT * SS];
__device__ __align__(16) bf16 g_glh[(size_t)BT * DFFN];
__device__ __align__(16) bf16 g_gll[(size_t)BT * DFFN];
__device__ __align__(16) bf16 g_w1h[(size_t)LLAYERS * DFFN * DD];
__device__ __align__(16) bf16 g_w1l[(size_t)LLAYERS * DFFN * DD];
__device__ __align__(16) bf16 g_w2h[(size_t)LLAYERS * DFFN * DD];
__device__ __align__(16) bf16 g_w2l[(size_t)LLAYERS * DFFN * DD];
__device__ __align__(16) bf16 g_w3h[(size_t)LLAYERS * DD * DFFN];
__device__ __align__(16) bf16 g_w3l[(size_t)LLAYERS * DD * DFFN];
__device__ __align__(16) bf16 g_bwh[LLAYERS * SS * DD];
__device__ __align__(16) bf16 g_bwl[LLAYERS * SS * DD];
__device__ __align__(16) bf16 g_cwh[LLAYERS * DD * SS];
__device__ __align__(16) bf16 g_cwl[LLAYERS * DD * SS];
__device__ __align__(16) __half g_hwh[(size_t)VV * DD];   // head weights: fp16 split
__device__ __align__(16) __half g_hwl[(size_t)VV * DD];

// ---------------- helpers ----------------
__device__ __forceinline__ uint32_t smem_u32(const void* p) {
    uint32_t a;
    asm("{ .reg .u64 t; cvta.to.shared.u64 t, %1; cvt.u32.u64 %0, t; }" : "=r"(a) : "l"(p));
    return a;
}
__device__ __forceinline__ void bf_split(float x, bf16& hi, bf16& lo) {
    hi = __float2bfloat16_rn(x);
    lo = __float2bfloat16_rn(x - __bfloat162float(hi));
}
__device__ __forceinline__ void fp16_split(float x, __half& hi, __half& lo) {
    hi = __float2half_rn(x);
    lo = __float2half_rn(x - __half2float(hi));
}
#define SWZ(o) ((o) ^ (((o) >> 3) & 0x70))

#if HAS_TCG
__device__ __forceinline__ uint32_t elect_one() {
    uint32_t r;
    asm volatile("{ .reg .pred p; elect.sync _|p, 0xFFFFFFFF; selp.b32 %0, 1, 0, p; }" : "=r"(r));
    return r;
}
static constexpr uint64_t DESC_BASE_SW128 =
    (uint64_t(2) << 61) | (uint64_t(1) << 46) | (uint64_t(64) << 32) | (uint64_t(1) << 16);
#define MAKE_SMEM_DESC(addr) (DESC_BASE_SW128 | ((uint64_t)((addr) >> 4) & 0x3FFF))

#define MBARRIER_INIT(mbar, cnt) \
    asm volatile("mbarrier.init.shared.b64 [%0], %1;" :: "r"((uint32_t)(mbar)), "r"((uint32_t)(cnt)) : "memory")
#define MBARRIER_INVAL(mbar) \
    asm volatile("mbarrier.inval.shared.b64 [%0];" :: "r"((uint32_t)(mbar)) : "memory")
#define MBARRIER_WAIT_PARITY(mbar_a, par) do { \
    uint32_t _m = (uint32_t)(mbar_a); uint32_t _p = (uint32_t)(par); uint32_t _d; \
    asm volatile("{ .reg .pred p; mbarrier.try_wait.parity.acquire.cta.shared::cta.b64 p, [%1], %2; selp.b32 %0, 1, 0, p; }" \
        : "=r"(_d) : "r"(_m), "r"(_p) : "memory"); \
    if (!_d) { \
        asm volatile("{ .reg .pred P1; WL_%=: mbarrier.try_wait.parity.acquire.cta.shared::cta.b64 P1, [%0], %1, 0x989680; @P1 bra.uni WD_%=; bra.uni WL_%=; WD_%=: }" \
            :: "r"(_m), "r"(_p) : "memory"); \
    } } while (0)

// .noinc is load-bearing: barrier init count = 256 (one arrive/thread/phase).
#define CPASYNC_ARRIVE(mbar) \
    asm volatile("cp.async.mbarrier.arrive.noinc.shared::cta.b64 [%0];" :: "r"((uint32_t)(mbar)) : "memory")

#define TCGEN05_ALLOC(slot, n) \
    asm volatile("tcgen05.alloc.cta_group::1.sync.aligned.shared::cta.b32 [%0], %1;" :: "r"((uint32_t)(slot)), "r"((uint32_t)(n)) : "memory")
#define TCGEN05_DEALLOC(t, n) \
    asm volatile("tcgen05.dealloc.cta_group::1.sync.aligned.b32 %0, %1;" :: "r"(t), "r"((uint32_t)(n)))
#define TCGEN05_RELINQ() \
    asm volatile("tcgen05.relinquish_alloc_permit.cta_group::1.sync.aligned;")
#define TCGEN05_COMMIT(mbar) \
    asm volatile("tcgen05.commit.cta_group::1.mbarrier::arrive::one.shared::cluster.b64 [%0];" :: "r"((uint32_t)(mbar)) : "memory")
#define TCGEN05_FENCE_AFTER() asm volatile("tcgen05.fence::after_thread_sync;" ::: "memory")
#define TCGEN05_WAIT_LD() asm volatile("tcgen05.wait::ld.sync.aligned;" ::: "memory")

#define TCGEN05_LD_X32(r, addr) \
    asm volatile("tcgen05.ld.sync.aligned.32x32b.x32.b32 {%0,%1,%2,%3,%4,%5,%6,%7,%8,%9,%10,%11,%12,%13,%14,%15,%16,%17,%18,%19,%20,%21,%22,%23,%24,%25,%26,%27,%28,%29,%30,%31}, [%32];" \
        : "=r"((r)[0]),"=r"((r)[1]),"=r"((r)[2]),"=r"((r)[3]),"=r"((r)[4]),"=r"((r)[5]),"=r"((r)[6]),"=r"((r)[7]), \
          "=r"((r)[8]),"=r"((r)[9]),"=r"((r)[10]),"=r"((r)[11]),"=r"((r)[12]),"=r"((r)[13]),"=r"((r)[14]),"=r"((r)[15]), \
          "=r"((r)[16]),"=r"((r)[17]),"=r"((r)[18]),"=r"((r)[19]),"=r"((r)[20]),"=r"((r)[21]),"=r"((r)[22]),"=r"((r)[23]), \
          "=r"((r)[24]),"=r"((r)[25]),"=r"((r)[26]),"=r"((r)[27]),"=r"((r)[28]),"=r"((r)[29]),"=r"((r)[30]),"=r"((r)[31]) \
        : "r"(addr))

__device__ __forceinline__ void mma_tc(uint32_t d, uint64_t ad, uint64_t bd,
                                       uint32_t idesc, uint32_t en) {
    asm volatile(
        "{ .reg .pred p; setp.ne.u32 p, %4, 0;\n\t"
        "tcgen05.mma.cta_group::1.kind::f16 [%0], %1, %2, %3, {%5, %5, %5, %5}, p; }"
        :: "r"(d), "l"(ad), "l"(bd), "r"(idesc), "r"(en), "r"(0u)
        : "memory");
}
#endif  // HAS_TCG

// ============ 3-term (bf16, DT=0) / 2-term (fp16, DT=1) compensated GEMM ============
// C[M,N] = A[M,K] @ B[N,K]^T; A,B pre-split hi/lo, SMEM row 128B = [hi 32 | lo 32] elems.
// DT=1 never references B-lo (terms Ah*Bh + Al*Bh), so B-lo loads are skipped.
template<int MT_, int NMMA_, bool SWIG_, int NST, int DT>
__global__ __launch_bounds__(256, 2) void gemm3x(
    const bf16* __restrict__ Ah, const bf16* __restrict__ Al,
    const bf16* __restrict__ Bh, const bf16* __restrict__ Bl,
    const bf16* __restrict__ B2h, const bf16* __restrict__ B2l,
    float* __restrict__ C, bf16* __restrict__ Oh, bf16* __restrict__ Ol,
    int N, int K, int epi,
    const float* __restrict__ aux0, const bf16* __restrict__ auxh, const bf16* __restrict__ auxl)
{
#if HAS_TCG
    constexpr int NTB  = SWIG_ ? 256 : NMMA_;
    constexpr int ROWS = MT_ + NTB;
    constexpr int STAGE = ROWS * 128;
    constexpr int NSUB = MT_ / 128;
    constexpr int TCOLS = (NSUB * NMMA_) < 128 ? 128 : (NSUB * NMMA_);
    constexpr int NSEG = ROWS * 8 / 256;
    constexpr int OUT_TILE = SWIG_ ? 128 : NMMA_;
    constexpr uint32_t TYB = (DT == 1) ? 0u : 1u;   // atype/btype: f16=0, bf16=1
    const uint32_t idesc = (1u << 4) | (TYB << 7) | (TYB << 10) | ((NMMA_ / 8) << 17) | (8u << 24);

    extern __shared__ char smem[];
    const uint32_t sbase = smem_u32(smem);
    const int tid = threadIdx.x;
    const int wid = tid >> 5;
    const int lane = tid & 31;
    const int m0 = blockIdx.x * MT_;
    const int n0 = blockIdx.y * OUT_TILE;

    if (tid == 0) {
        #pragma unroll
        for (int s = 0; s < NST; s++) {
            MBARRIER_INIT(sbase + s * 16, 256);
            MBARRIER_INIT(sbase + s * 16 + 8, 1);
        }
    }
    if (wid == 0) { TCGEN05_ALLOC(sbase + 64, TCOLS); TCGEN05_RELINQ(); }
    __syncthreads();
    uint32_t tmem;
    asm volatile("ld.shared.b32 %0, [%1];" : "=r"(tmem) : "r"(sbase + 64));

    // per-thread loader state
    const bf16* gp[NSEG];
    uint32_t so[NSEG];
    int koff[NSEG];
    bool nok[NSEG];
    #pragma unroll
    for (int i = 0; i < NSEG; i++) {
        int f = i * 256 + tid;
        int row = f >> 3, s8 = f & 7;
        int half = s8 >> 2, q = s8 & 3;
        koff[i] = q * 8;
        so[i] = SWZ(row * 128 + half * 64 + q * 16);
        if (row < MT_) {
            gp[i] = (half ? Al : Ah) + (size_t)(m0 + row) * K + q * 8;
            nok[i] = true;
        } else {
            int r2 = row - MT_;
            int n;
            const bf16* ph;
            if (SWIG_ && r2 >= 128) { n = n0 + r2 - 128; ph = half ? B2l : B2h; }
            else                    { n = n0 + r2;       ph = half ? Bl  : Bh; }
            nok[i] = (n < N);
            if (DT == 1 && half == 1) nok[i] = false;   // B-lo unused in fp16x2 -> skip load
            if (n >= N) n = 0;
            gp[i] = ph + (size_t)n * K + q * 8;
        }
    }

    const int nch = (K + 31) / 32;

    auto cp_chunk = [&](int c, int st) {
        int k0 = c * 32;
        uint32_t sb2 = sbase + 1024 + st * STAGE;
        #pragma unroll
        for (int i = 0; i < NSEG; i++) {
            uint32_t sz = (nok[i] && (k0 + koff[i]) < K) ? 16u : 0u;   // sz=0 -> zero-fill
            asm volatile("cp.async.cg.shared.global [%0], [%1], 16, %2;"
                         :: "r"(sb2 + so[i]), "l"(gp[i] + k0), "r"(sz));
        }
    };

    #pragma unroll
    for (int p = 0; p < NST - 1; p++) {
        if (p < nch) { cp_chunk(p, p); CPASYNC_ARRIVE(sbase + p * 16); }
    }

    for (int ci = 0; ci < nch; ci++) {
        int sc = ci % NST;
        int nxt = ci + NST - 1;
        if (nxt < nch) {
            int sn = nxt % NST;
            if (nxt >= NST)
                MBARRIER_WAIT_PARITY(sbase + sn * 16 + 8, ((nxt / NST) + 1) & 1);
            cp_chunk(nxt, sn);
            CPASYNC_ARRIVE(sbase + sn * 16);
        }
        if (wid == 0 && elect_one()) {
            MBARRIER_WAIT_PARITY(sbase + sc * 16, (ci / NST) & 1);
            asm volatile("fence.proxy.async.shared::cta;" ::: "memory");
            uint32_t sa = sbase + 1024 + sc * STAGE;
            uint64_t ad0 = MAKE_SMEM_DESC(sa);
            uint64_t bd0 = MAKE_SMEM_DESC(sa + MT_ * 128);
            #pragma unroll
            for (int s = 0; s < NSUB; s++) {
                uint32_t d = tmem + s * NMMA_;
                uint64_t ad = ad0 + s * 1024;
                #pragma unroll
                for (int ks = 0; ks < 2; ks++) {
                    mma_tc(d, ad + ks * 2,     bd0 + ks * 2,     idesc, (ci > 0 || ks > 0) ? 1u : 0u);
                    mma_tc(d, ad + 4 + ks * 2, bd0 + ks * 2,     idesc, 1u);
                    if (DT == 0)   // 3rd term only for bf16x3; fp16x2 drops hi*lo
                        mma_tc(d, ad + ks * 2, bd0 + 4 + ks * 2, idesc, 1u);
                }
            }
            TCGEN05_COMMIT(sbase + sc * 16 + 8);
        }
    }
    MBARRIER_WAIT_PARITY(sbase + ((nch - 1) % NST) * 16 + 8, ((nch - 1) / NST) & 1);
    TCGEN05_FENCE_AFTER();

    // ---------------- epilogue ----------------
    const int sub = wid >> 2;
    if (epi == 5) {
        int m = m0 + (wid & 3) * 32 + lane;
        #pragma unroll
        for (int jb = 0; jb < 2; jb++) {
            int cb = sub * 64 + jb * 32;
            uint32_t r1[32], r2[32];
            TCGEN05_LD_X32(r1, tmem + cb);
            TCGEN05_LD_X32(r2, tmem + 128 + cb);
            TCGEN05_WAIT_LD();
            #pragma unroll
            for (int q = 0; q < 8; q++) {
                int n = n0 + cb + q * 4;
                if (n < N) {
                    bf16 oh[4], ol[4];
                    #pragma unroll
                    for (int e = 0; e < 4; e++) {
                        float a = __uint_as_float(r1[q * 4 + e]);
                        float b = __uint_as_float(r2[q * 4 + e]);
                        float v = (a / (1.0f + expf(-a))) * b;
                        bf_split(v, oh[e], ol[e]);
                    }
                    *(uint2*)(Oh + (size_t)m * N + n) = *(uint2*)oh;
                    *(uint2*)(Ol + (size_t)m * N + n) = *(uint2*)ol;
                }
            }
        }
    } else {
        uint32_t tb;
        int m, c0, c1;
        if (MT_ == 256) { tb = tmem + sub * NMMA_; m = m0 + sub * 128 + (wid & 3) * 32 + lane; c0 = 0; c1 = NMMA_; }
        else            { tb = tmem; m = m0 + (wid & 3) * 32 + lane; c0 = sub * (NMMA_ / 2); c1 = c0 + NMMA_ / 2; }
        float* Crow = C + (size_t)m * N + n0;
        for (int cb = c0; cb < c1; cb += 32) {
            uint32_t r[32];
            TCGEN05_LD_X32(r, tb + cb);
            TCGEN05_WAIT_LD();
            #pragma unroll
            for (int q = 0; q < 8; q++) {
                int nrel = cb + q * 4;
                float4 v = make_float4(__uint_as_float(r[q * 4 + 0]), __uint_as_float(r[q * 4 + 1]),
                                       __uint_as_float(r[q * 4 + 2]), __uint_as_float(r[q * 4 + 3]));
                if (epi == 1) {
                    float4 hv = *(float4*)(Crow + nrel);
                    size_t xi = (size_t)m * DD + n0 + nrel;
                    __nv_bfloat162 xh0 = *(const __nv_bfloat162*)(auxh + xi);
                    __nv_bfloat162 xh1 = *(const __nv_bfloat162*)(auxh + xi + 2);
                    __nv_bfloat162 xl0 = *(const __nv_bfloat162*)(auxl + xi);
                    __nv_bfloat162 xl1 = *(const __nv_bfloat162*)(auxl + xi + 2);
                    float4 dv = *(const float4*)(aux0 + n0 + nrel);
                    v.x += hv.x + dv.x * (__bfloat162float(xh0.x) + __bfloat162float(xl0.x));
                    v.y += hv.y + dv.y * (__bfloat162float(xh0.y) + __bfloat162float(xl0.y));
                    v.z += hv.z + dv.z * (__bfloat162float(xh1.x) + __bfloat162float(xl1.x));
                    v.w += hv.w + dv.w * (__bfloat162float(xh1.y) + __bfloat162float(xl1.y));
                    *(float4*)(Crow + nrel) = v;
                } else if (epi == 3) {
                    float4 hv = *(float4*)(Crow + nrel);
                    v.x += hv.x; v.y += hv.y; v.z += hv.z; v.w += hv.w;
                    *(float4*)(Crow + nrel) = v;
                } else if (epi == 4) {
                    float4 bv = *(const float4*)(aux0 + n0 + nrel);
                    v.x += bv.x; v.y += bv.y; v.z += bv.z; v.w += bv.w;
                    // streaming store: huge logits buffer must not evict headW from L2
                    asm volatile("st.global.cs.v4.f32 [%0], {%1, %2, %3, %4};"
                                 :: "l"(Crow + nrel), "f"(v.x), "f"(v.y), "f"(v.z), "f"(v.w)
                                 : "memory");
                } else {
                    *(float4*)(Crow + nrel) = v;
                }
            }
        }
    }

    __syncthreads();
    if (tid == 0) {
        #pragma unroll
        for (int s = 0; s < NST; s++) { MBARRIER_INVAL(sbase + s * 16); MBARRIER_INVAL(sbase + s * 16 + 8); }
    }
    __syncthreads();
    if (wid == 0) TCGEN05_DEALLOC(tmem, TCOLS);
#else
    // -------- generic-arch fallback (correct, slow) --------
    const int tid = threadIdx.x;
    constexpr int OUT_TILE = SWIG_ ? 128 : NMMA_;
    const int m0 = blockIdx.x * MT_;
    const int n0 = blockIdx.y * OUT_TILE;
    auto ld = [](const bf16* p, size_t i) -> float {
        if (DT == 1) return __half2float(((const __half*)p)[i]);
        return __bfloat162float(p[i]);
    };
    for (int idx = tid; idx < MT_ * OUT_TILE; idx += 256) {
        int mi = m0 + idx / OUT_TILE;
        int n = n0 + idx % OUT_TILE;
        if (n >= N) continue;
        if (SWIG_) {
            float a = 0.f, b = 0.f;
            for (int k = 0; k < K; k++) {
                float av = ld(Ah, (size_t)mi * K + k) + ld(Al, (size_t)mi * K + k);
                a += av * (ld(Bh, (size_t)n * K + k) + ld(Bl, (size_t)n * K + k));
                b += av * (ld(B2h, (size_t)n * K + k) + ld(B2l, (size_t)n * K + k));
            }
            float v = (a / (1.0f + expf(-a))) * b;
            bf16 oh, ol; bf_split(v, oh, ol);
            Oh[(size_t)mi * N + n] = oh;
            Ol[(size_t)mi * N + n] = ol;
        } else {
            float acc = 0.f;
            for (int k = 0; k < K; k++) {
                float bv = ld(Bh, (size_t)n * K + k) + ((DT == 0) ? ld(Bl, (size_t)n * K + k) : 0.f);
                acc += (ld(Ah, (size_t)mi * K + k) + ld(Al, (size_t)mi * K + k)) * bv;
            }
            size_t ci = (size_t)mi * N + n;
            if (epi == 1)      acc += C[ci] + aux0[n] * (__bfloat162float(auxh[(size_t)mi * DD + n]) +
                                                         __bfloat162float(auxl[(size_t)mi * DD + n]));
            else if (epi == 3) acc += C[ci];
            else if (epi == 4) acc += aux0[n];
            C[ci] = acc;
        }
    }
#endif
}

// ---------------- fused split: weights -> hi/lo (head in fp16, rest bf16) ----------------
__global__ void split_all(const float* __restrict__ headW, const float* __restrict__ w1,
                          const float* __restrict__ w2, const float* __restrict__ w3,
                          const float* __restrict__ Bw, const float* __restrict__ Cw) {
    const long C0 = (long)VV * DD / 4;
    const long CW = (long)LLAYERS * DFFN * DD / 4;
    const long CB = (long)LLAYERS * SS * DD / 4;
    long j = (long)blockIdx.x * 256 + threadIdx.x;
    if (j < C0) {   // head weights: fp16 split
        float4 v = ((const float4*)headW)[j];
        __half h[4], l[4];
        fp16_split(v.x, h[0], l[0]);
        fp16_split(v.y, h[1], l[1]);
        fp16_split(v.z, h[2], l[2]);
        fp16_split(v.w, h[3], l[3]);
        ((uint2*)g_hwh)[j] = *(uint2*)h;
        ((uint2*)g_hwl)[j] = *(uint2*)l;
        return;
    }
    j -= C0;
    const float* src; bf16 *hi, *lo;
    if (j < CW)              { src = w1; hi = g_w1h; lo = g_w1l; }
    else if ((j -= CW) < CW) { src = w2; hi = g_w2h; lo = g_w2l; }
    else if ((j -= CW) < CW) { src = w3; hi = g_w3h; lo = g_w3l; }
    else if ((j -= CW) < CB) { src = Bw; hi = g_bwh; lo = g_bwl; }
    else if ((j -= CB) < CB) { src = Cw; hi = g_cwh; lo = g_cwl; }
    else return;
    float4 v = ((const float4*)src)[j];
    bf16 h[4], l[4];
    bf_split(v.x, h[0], l[0]);
    bf_split(v.y, h[1], l[1]);
    bf_split(v.z, h[2], l[2]);
    bf_split(v.w, h[3], l[3]);
    ((uint2*)hi)[j] = *(uint2*)h;
    ((uint2*)lo)[j] = *(uint2*)l;
}

// ---------------- embed ----------------
__global__ void embed_k(const int* __restrict__ x, const float* __restrict__ emb,
                        const float* __restrict__ pos, float* __restrict__ h) {
    int row = blockIdx.x;
    int t = row & (TT - 1);
    int tid = threadIdx.x;
    int v = x[row];
    float4 e = ((const float4*)(emb + (size_t)v * DD))[tid];
    float4 p = ((const float4*)(pos + (size_t)t * DD))[tid];
    ((float4*)(h + (size_t)row * DD))[tid] =
        make_float4(e.x + p.x, e.y + p.y, e.z + p.z, e.w + p.w);
}

// ---------------- layernorm D=512 -> split hi/lo (bf16, or fp16 when hmode=1) ----------------
__global__ void ln512(const float* __restrict__ X, bf16* __restrict__ Yh, bf16* __restrict__ Yl,
                      const float* __restrict__ w, const float* __restrict__ bvec, int hmode) {
    int row = blockIdx.x;
    int tid = threadIdx.x;
    float4 v = ((const float4*)(X + (size_t)row * DD))[tid];
    float sum = v.x + v.y + v.z + v.w;
    float sq  = v.x * v.x + v.y * v.y + v.z * v.z + v.w * v.w;
    #pragma unroll
    for (int o = 16; o > 0; o >>= 1) {
        sum += __shfl_xor_sync(0xffffffffu, sum, o);
        sq  += __shfl_xor_sync(0xffffffffu, sq, o);
    }
    __shared__ float s1[4], s2[4];
    if ((tid & 31) == 0) { s1[tid >> 5] = sum; s2[tid >> 5] = sq; }
    __syncthreads();
    sum = s1[0] + s1[1] + s1[2] + s1[3];
    sq  = s2[0] + s2[1] + s2[2] + s2[3];
    float mu = sum * (1.0f / DD);
    float var = sq * (1.0f / DD) - mu * mu;
    float rs = rsqrtf(var + 1e-5f);
    float4 wv = ((const float4*)w)[tid];
    float4 bv = ((const float4*)bvec)[tid];
    float o[4];
    o[0] = (v.x - mu) * rs * wv.x + bv.x;
    o[1] = (v.y - mu) * rs * wv.y + bv.y;
    o[2] = (v.z - mu) * rs * wv.z + bv.z;
    o[3] = (v.w - mu) * rs * wv.w + bv.w;
    if (hmode) {
        __half h[4], l[4];
        #pragma unroll
        for (int e = 0; e < 4; e++) fp16_split(o[e], h[e], l[e]);
        *(uint2*)((__half*)Yh + (size_t)row * DD + tid * 4) = *(uint2*)h;
        *(uint2*)((__half*)Yl + (size_t)row * DD + tid * 4) = *(uint2*)l;
    } else {
        bf16 h[4], l[4];
        #pragma unroll
        for (int e = 0; e < 4; e++) bf_split(o[e], h[e], l[e]);
        *(uint2*)(Yh + (size_t)row * DD + tid * 4) = *(uint2*)h;
        *(uint2*)(Yl + (size_t)row * DD + tid * 4) = *(uint2*)l;
    }
}

// ---------------- SSM scan -> bf16 hi/lo ----------------
__global__ void ssm_scan(const float* __restrict__ Bu, bf16* __restrict__ Hh,
                         bf16* __restrict__ Hl, const float* __restrict__ loglam) {
    const int SEG = TT / 128;     // 16
    int b  = blockIdx.x >> 5;
    int cg = blockIdx.x & 31;
    int sx = threadIdx.x;         // 0..7
    int sy = threadIdx.y;         // 0..127
    int s = cg * 8 + sx;
    float lam = 1.0f / (1.0f + expf(-loglam[s]));
    size_t base = ((size_t)(b * TT + sy * SEG)) * SS + s;

    float h = 0.0f;
    #pragma unroll
    for (int i = 0; i < SEG; i++) h = lam * h + Bu[base + (size_t)i * SS];

    __shared__ float carry[128][9];
    __shared__ float cin[128][9];
    carry[sy][sx] = h;
    __syncthreads();
    if (sy == 0) {
        float lamS = lam;
        #pragma unroll
        for (int q = 0; q < 4; q++) lamS *= lamS;     // lam^16
        float c = 0.0f;
        for (int j = 0; j < 128; j++) { cin[j][sx] = c; c = lamS * c + carry[j][sx]; }
    }
    __syncthreads();

    h = cin[sy][sx];
    #pragma unroll
    for (int i = 0; i < SEG; i++) {
        size_t idx = base + (size_t)i * SS;
        h = lam * h + Bu[idx];
        bf16 hb, lb;
        bf_split(h, hb, lb);
        Hh[idx] = hb;
        Hl[idx] = lb;
    }
}

// ---------------- launch ----------------
#define SM_SMALL (1024 + 4 * (192 * 128))   // MT=128, NT=64, NST=4
#define SM_SWIG  (1024 + 2 * (384 * 128))   // MT=128, NT=256, NST=2
#define SM_HEAD  (1024 + 2 * (384 * 128))   // MT=128, NT=256, NST=2

extern "C" void kernel_launch(void* const* d_in, const int* in_sizes, int n_in,
                              void* d_out, int out_size) {
    const int*   x      = (const int*)  d_in[0];
    const float* emb    = (const float*)d_in[1];
    const float* pos    = (const float*)d_in[2];
    const float* loglam = (const float*)d_in[3];
    const float* Bw     = (const float*)d_in[4];
    const float* Cw     = (const float*)d_in[5];
    const float* Dp     = (const float*)d_in[6];
    const float* n1w    = (const float*)d_in[7];
    const float* n1b    = (const float*)d_in[8];
    const float* n2w    = (const float*)d_in[9];
    const float* n2b    = (const float*)d_in[10];
    const float* w1     = (const float*)d_in[11];
    const float* w2     = (const float*)d_in[12];
    const float* w3     = (const float*)d_in[13];
    const float* now    = (const float*)d_in[14];
    const float* nob    = (const float*)d_in[15];
    const float* headW  = (const float*)d_in[16];
    const float* headb  = (const float*)d_in[17];
    float* out = (float*)d_out;

    float *h, *bu;
    bf16 *xnh, *xnl, *buh, *bul, *glh, *gll;
    bf16 *w1h, *w1l, *w2h, *w2l, *w3h, *w3l, *bwh, *bwl, *cwh, *cwl;
    __half *hwh, *hwl;
    cudaGetSymbolAddress((void**)&h,   g_h);
    cudaGetSymbolAddress((void**)&xnh, g_xnh);
    cudaGetSymbolAddress((void**)&xnl, g_xnl);
    cudaGetSymbolAddress((void**)&bu,  g_bu);
    cudaGetSymbolAddress((void**)&buh, g_buh);
    cudaGetSymbolAddress((void**)&bul, g_bul);
    cudaGetSymbolAddress((void**)&glh, g_glh);
    cudaGetSymbolAddress((void**)&gll, g_gll);
    cudaGetSymbolAddress((void**)&w1h, g_w1h);
    cudaGetSymbolAddress((void**)&w1l, g_w1l);
    cudaGetSymbolAddress((void**)&w2h, g_w2h);
    cudaGetSymbolAddress((void**)&w2l, g_w2l);
    cudaGetSymbolAddress((void**)&w3h, g_w3h);
    cudaGetSymbolAddress((void**)&w3l, g_w3l);
    cudaGetSymbolAddress((void**)&bwh, g_bwh);
    cudaGetSymbolAddress((void**)&bwl, g_bwl);
    cudaGetSymbolAddress((void**)&cwh, g_cwh);
    cudaGetSymbolAddress((void**)&cwl, g_cwl);
    cudaGetSymbolAddress((void**)&hwh, g_hwh);
    cudaGetSymbolAddress((void**)&hwl, g_hwl);

    cudaFuncSetAttribute((const void*)gemm3x<128, 64, false, 4, 0>,
                         cudaFuncAttributeMaxDynamicSharedMemorySize, SM_SMALL);
    cudaFuncSetAttribute((const void*)gemm3x<128, 256, true, 2, 0>,
                         cudaFuncAttributeMaxDynamicSharedMemorySize, SM_SWIG);
    cudaFuncSetAttribute((const void*)gemm3x<128, 256, false, 2, 1>,
                         cudaFuncAttributeMaxDynamicSharedMemorySize, SM_HEAD);

    // one fused split launch
    {
        long total = (long)VV * DD / 4 + 3L * LLAYERS * DFFN * DD / 4 + 2L * LLAYERS * SS * DD / 4;
        split_all<<<(unsigned)((total + 255) / 256), 256>>>(headW, w1, w2, w3, Bw, Cw);
    }

    embed_k<<<BT, 128>>>(x, emb, pos, h);

    for (int l = 0; l < LLAYERS; l++) {
        ln512<<<BT, 128>>>(h, xnh, xnl, n1w + l * DD, n1b + l * DD, 0);
        // Bu = xn @ Bw^T   [4096,256]
        gemm3x<128, 64, false, 4, 0><<<dim3(32, 4), 256, SM_SMALL>>>(
            xnh, xnl, bwh + (size_t)l * SS * DD, bwl + (size_t)l * SS * DD,
            nullptr, nullptr, bu, nullptr, nullptr, SS, DD, 0, nullptr, nullptr, nullptr);
        ssm_scan<<<64, dim3(8, 128)>>>(bu, buh, bul, loglam + l * SS);
        // h += hscan @ Cw^T + Dp*xn   [4096,512]
        gemm3x<128, 64, false, 4, 0><<<dim3(32, 8), 256, SM_SMALL>>>(
            buh, bul, cwh + (size_t)l * DD * SS, cwl + (size_t)l * DD * SS,
            nullptr, nullptr, h, nullptr, nullptr, DD, SS, 1, Dp + l * DD, xnh, xnl);
        ln512<<<BT, 128>>>(h, xnh, xnl, n2w + l * DD, n2b + l * DD, 0);
        // gl = silu(xn@w1^T)*(xn@w2^T)   [4096,1368]
        gemm3x<128, 256, true, 2, 0><<<dim3(32, 11), 256, SM_SWIG>>>(
            xnh, xnl, w1h + (size_t)l * DFFN * DD, w1l + (size_t)l * DFFN * DD,
            w2h + (size_t)l * DFFN * DD, w2l + (size_t)l * DFFN * DD,
            nullptr, glh, gll, DFFN, DD, 5, nullptr, nullptr, nullptr);
        // h += gl @ w3^T   [4096,512]
        gemm3x<128, 64, false, 4, 0><<<dim3(32, 8), 256, SM_SMALL>>>(
            glh, gll, w3h + (size_t)l * DD * DFFN, w3l + (size_t)l * DD * DFFN,
            nullptr, nullptr, h, nullptr, nullptr, DD, DFFN, 3, nullptr, nullptr, nullptr);
    }

    // final LN -> fp16 hi/lo (head path)
    ln512<<<BT, 128>>>(h, xnh, xnl, now, nob, 1);
    // logits = xn @ headW^T + headb   [4096,32000]  — fp16 2-term, B-lo loads skipped
    gemm3x<128, 256, false, 2, 1><<<dim3(32, 125), 256, SM_HEAD>>>(
        xnh, xnl, (bf16*)hwh, (bf16*)hwl, nullptr, nullptr, out, nullptr, nullptr,
        VV, DD, 4, headb, nullptr, nullptr);
}

// round 13
// speedup vs baseline: 1.5511x; 1.5511x over previous
#include <cuda_runtime.h>
#include <cuda_bf16.h>
#include <cuda_fp16.h>
#include <cstdint>
#include <math.h>

#define BT 4096
#define TT 2048
#define DD 512
#define SS 256
#define LLAYERS 4
#define DFFN 1368
#define VV 32000

#if defined(__CUDA_ARCH__) && defined(__CUDA_ARCH_FEAT_SM103_ALL)
#define HAS_TCG 1
#else
#define HAS_TCG 0
#endif

typedef __nv_bfloat16 bf16;

// ---------------- scratch ----------------
__device__ float g_h[BT * DD];
__device__ __align__(16) bf16 g_xnh[BT * DD];   // bf16 pairs (layers) or fp16 bits (final LN)
__device__ __align__(16) bf16 g_xnl[BT * DD];
__device__ float g_bu[BT * SS];
__device__ __align__(16) bf16 g_buh[BT * SS];
__device__ __align__(16) bf16 g_bul[BT * SS];
__device__ __align__(16) bf16 g_glh[(size_t)BT * DFFN];
__device__ __align__(16) bf16 g_gll[(size_t)BT * DFFN];
__device__ __align__(16) bf16 g_w1h[(size_t)LLAYERS * DFFN * DD];
__device__ __align__(16) bf16 g_w1l[(size_t)LLAYERS * DFFN * DD];
__device__ __align__(16) bf16 g_w2h[(size_t)LLAYERS * DFFN * DD];
__device__ __align__(16) bf16 g_w2l[(size_t)LLAYERS * DFFN * DD];
__device__ __align__(16) bf16 g_w3h[(size_t)LLAYERS * DD * DFFN];
__device__ __align__(16) bf16 g_w3l[(size_t)LLAYERS * DD * DFFN];
__device__ __align__(16) bf16 g_bwh[LLAYERS * SS * DD];
__device__ __align__(16) bf16 g_bwl[LLAYERS * SS * DD];
__device__ __align__(16) bf16 g_cwh[LLAYERS * DD * SS];
__device__ __align__(16) bf16 g_cwl[LLAYERS * DD * SS];
__device__ __align__(16) __half g_hwh[(size_t)VV * DD];   // head weights: fp16 split
__device__ __align__(16) __half g_hwl[(size_t)VV * DD];

// ---------------- helpers ----------------
__device__ __forceinline__ uint32_t smem_u32(const void* p) {
    uint32_t a;
    asm("{ .reg .u64 t; cvta.to.shared.u64 t, %1; cvt.u32.u64 %0, t; }" : "=r"(a) : "l"(p));
    return a;
}
__device__ __forceinline__ void bf_split(float x, bf16& hi, bf16& lo) {
    hi = __float2bfloat16_rn(x);
    lo = __float2bfloat16_rn(x - __bfloat162float(hi));
}
__device__ __forceinline__ void fp16_split(float x, __half& hi, __half& lo) {
    hi = __float2half_rn(x);
    lo = __float2half_rn(x - __half2float(hi));
}
#define SWZ(o) ((o) ^ (((o) >> 3) & 0x70))

#if HAS_TCG
__device__ __forceinline__ uint32_t elect_one() {
    uint32_t r;
    asm volatile("{ .reg .pred p; elect.sync _|p, 0xFFFFFFFF; selp.b32 %0, 1, 0, p; }" : "=r"(r));
    return r;
}
static constexpr uint64_t DESC_BASE_SW128 =
    (uint64_t(2) << 61) | (uint64_t(1) << 46) | (uint64_t(64) << 32) | (uint64_t(1) << 16);
#define MAKE_SMEM_DESC(addr) (DESC_BASE_SW128 | ((uint64_t)((addr) >> 4) & 0x3FFF))

#define MBARRIER_INIT(mbar, cnt) \
    asm volatile("mbarrier.init.shared.b64 [%0], %1;" :: "r"((uint32_t)(mbar)), "r"((uint32_t)(cnt)) : "memory")
#define MBARRIER_INVAL(mbar) \
    asm volatile("mbarrier.inval.shared.b64 [%0];" :: "r"((uint32_t)(mbar)) : "memory")
#define MBARRIER_WAIT_PARITY(mbar_a, par) do { \
    uint32_t _m = (uint32_t)(mbar_a); uint32_t _p = (uint32_t)(par); uint32_t _d; \
    asm volatile("{ .reg .pred p; mbarrier.try_wait.parity.acquire.cta.shared::cta.b64 p, [%1], %2; selp.b32 %0, 1, 0, p; }" \
        : "=r"(_d) : "r"(_m), "r"(_p) : "memory"); \
    if (!_d) { \
        asm volatile("{ .reg .pred P1; WL_%=: mbarrier.try_wait.parity.acquire.cta.shared::cta.b64 P1, [%0], %1, 0x989680; @P1 bra.uni WD_%=; bra.uni WL_%=; WD_%=: }" \
            :: "r"(_m), "r"(_p) : "memory"); \
    } } while (0)

// .noinc is load-bearing: barrier init count = 256 (one arrive/thread/phase).
#define CPASYNC_ARRIVE(mbar) \
    asm volatile("cp.async.mbarrier.arrive.noinc.shared::cta.b64 [%0];" :: "r"((uint32_t)(mbar)) : "memory")

#define TCGEN05_ALLOC(slot, n) \
    asm volatile("tcgen05.alloc.cta_group::1.sync.aligned.shared::cta.b32 [%0], %1;" :: "r"((uint32_t)(slot)), "r"((uint32_t)(n)) : "memory")
#define TCGEN05_DEALLOC(t, n) \
    asm volatile("tcgen05.dealloc.cta_group::1.sync.aligned.b32 %0, %1;" :: "r"(t), "r"((uint32_t)(n)))
#define TCGEN05_RELINQ() \
    asm volatile("tcgen05.relinquish_alloc_permit.cta_group::1.sync.aligned;")
#define TCGEN05_COMMIT(mbar) \
    asm volatile("tcgen05.commit.cta_group::1.mbarrier::arrive::one.shared::cluster.b64 [%0];" :: "r"((uint32_t)(mbar)) : "memory")
#define TCGEN05_FENCE_AFTER() asm volatile("tcgen05.fence::after_thread_sync;" ::: "memory")
#define TCGEN05_WAIT_LD() asm volatile("tcgen05.wait::ld.sync.aligned;" ::: "memory")

#define TCGEN05_LD_X32(r, addr) \
    asm volatile("tcgen05.ld.sync.aligned.32x32b.x32.b32 {%0,%1,%2,%3,%4,%5,%6,%7,%8,%9,%10,%11,%12,%13,%14,%15,%16,%17,%18,%19,%20,%21,%22,%23,%24,%25,%26,%27,%28,%29,%30,%31}, [%32];" \
        : "=r"((r)[0]),"=r"((r)[1]),"=r"((r)[2]),"=r"((r)[3]),"=r"((r)[4]),"=r"((r)[5]),"=r"((r)[6]),"=r"((r)[7]), \
          "=r"((r)[8]),"=r"((r)[9]),"=r"((r)[10]),"=r"((r)[11]),"=r"((r)[12]),"=r"((r)[13]),"=r"((r)[14]),"=r"((r)[15]), \
          "=r"((r)[16]),"=r"((r)[17]),"=r"((r)[18]),"=r"((r)[19]),"=r"((r)[20]),"=r"((r)[21]),"=r"((r)[22]),"=r"((r)[23]), \
          "=r"((r)[24]),"=r"((r)[25]),"=r"((r)[26]),"=r"((r)[27]),"=r"((r)[28]),"=r"((r)[29]),"=r"((r)[30]),"=r"((r)[31]) \
        : "r"(addr))

__device__ __forceinline__ void mma_tc(uint32_t d, uint64_t ad, uint64_t bd,
                                       uint32_t idesc, uint32_t en) {
    asm volatile(
        "{ .reg .pred p; setp.ne.u32 p, %4, 0;\n\t"
        "tcgen05.mma.cta_group::1.kind::f16 [%0], %1, %2, %3, {%5, %5, %5, %5}, p; }"
        :: "r"(d), "l"(ad), "l"(bd), "r"(idesc), "r"(en), "r"(0u)
        : "memory");
}
#endif  // HAS_TCG

// ============ 3-term (bf16, DT=0) / 2-term (fp16, DT=1) compensated GEMM ============
// C[M,N] = A[M,K] @ B[N,K]^T; A,B pre-split hi/lo, SMEM row 128B = [hi 32 | lo 32] elems.
// DT=1 never references B-lo (terms Ah*Bh + Al*Bh), so B-lo loads are skipped (zero-fill).
template<int MT_, int NMMA_, bool SWIG_, int NST, int DT>
__global__ __launch_bounds__(256, 2) void gemm3x(
    const bf16* __restrict__ Ah, const bf16* __restrict__ Al,
    const bf16* __restrict__ Bh, const bf16* __restrict__ Bl,
    const bf16* __restrict__ B2h, const bf16* __restrict__ B2l,
    float* __restrict__ C, bf16* __restrict__ Oh, bf16* __restrict__ Ol,
    int N, int K, int epi,
    const float* __restrict__ aux0, const bf16* __restrict__ auxh, const bf16* __restrict__ auxl)
{
#if HAS_TCG
    constexpr int NTB  = SWIG_ ? 256 : NMMA_;
    constexpr int ROWS = MT_ + NTB;
    constexpr int STAGE = ROWS * 128;
    constexpr int NSUB = MT_ / 128;
    constexpr int TCOLS = (NSUB * NMMA_) < 128 ? 128 : (NSUB * NMMA_);
    constexpr int NSEG = ROWS * 8 / 256;
    constexpr int OUT_TILE = SWIG_ ? 128 : NMMA_;
    constexpr uint32_t TYB = (DT == 1) ? 0u : 1u;   // atype/btype: f16=0, bf16=1
    const uint32_t idesc = (1u << 4) | (TYB << 7) | (TYB << 10) | ((NMMA_ / 8) << 17) | (8u << 24);

    extern __shared__ char smem[];
    const uint32_t sbase = smem_u32(smem);
    const int tid = threadIdx.x;
    const int wid = tid >> 5;
    const int lane = tid & 31;
    const int m0 = blockIdx.x * MT_;
    const int n0 = blockIdx.y * OUT_TILE;

    if (tid == 0) {
        #pragma unroll
        for (int s = 0; s < NST; s++) {
            MBARRIER_INIT(sbase + s * 16, 256);
            MBARRIER_INIT(sbase + s * 16 + 8, 1);
        }
    }
    if (wid == 0) { TCGEN05_ALLOC(sbase + 64, TCOLS); TCGEN05_RELINQ(); }
    __syncthreads();
    uint32_t tmem;
    asm volatile("ld.shared.b32 %0, [%1];" : "=r"(tmem) : "r"(sbase + 64));

    // per-thread loader state
    const bf16* gp[NSEG];
    uint32_t so[NSEG];
    int koff[NSEG];
    bool nok[NSEG];
    #pragma unroll
    for (int i = 0; i < NSEG; i++) {
        int f = i * 256 + tid;
        int row = f >> 3, s8 = f & 7;
        int half = s8 >> 2, q = s8 & 3;
        koff[i] = q * 8;
        so[i] = SWZ(row * 128 + half * 64 + q * 16);
        if (row < MT_) {
            gp[i] = (half ? Al : Ah) + (size_t)(m0 + row) * K + q * 8;
            nok[i] = true;
        } else {
            int r2 = row - MT_;
            int n;
            const bf16* ph;
            if (SWIG_ && r2 >= 128) { n = n0 + r2 - 128; ph = half ? B2l : B2h; }
            else                    { n = n0 + r2;       ph = half ? Bl  : Bh; }
            nok[i] = (n < N);
            if (DT == 1 && half == 1) nok[i] = false;   // B-lo unused in fp16x2 -> skip load
            if (n >= N) n = 0;
            gp[i] = ph + (size_t)n * K + q * 8;
        }
    }

    const int nch = (K + 31) / 32;

    auto cp_chunk = [&](int c, int st) {
        int k0 = c * 32;
        uint32_t sb2 = sbase + 1024 + st * STAGE;
        #pragma unroll
        for (int i = 0; i < NSEG; i++) {
            uint32_t sz = (nok[i] && (k0 + koff[i]) < K) ? 16u : 0u;   // sz=0 -> zero-fill
            asm volatile("cp.async.cg.shared.global [%0], [%1], 16, %2;"
                         :: "r"(sb2 + so[i]), "l"(gp[i] + k0), "r"(sz));
        }
    };

    #pragma unroll
    for (int p = 0; p < NST - 1; p++) {
        if (p < nch) { cp_chunk(p, p); CPASYNC_ARRIVE(sbase + p * 16); }
    }

    for (int ci = 0; ci < nch; ci++) {
        int sc = ci % NST;
        int nxt = ci + NST - 1;
        if (nxt < nch) {
            int sn = nxt % NST;
            if (nxt >= NST)
                MBARRIER_WAIT_PARITY(sbase + sn * 16 + 8, ((nxt / NST) + 1) & 1);
            cp_chunk(nxt, sn);
            CPASYNC_ARRIVE(sbase + sn * 16);
        }
        if (wid == 0 && elect_one()) {
            MBARRIER_WAIT_PARITY(sbase + sc * 16, (ci / NST) & 1);
            asm volatile("fence.proxy.async.shared::cta;" ::: "memory");
            uint32_t sa = sbase + 1024 + sc * STAGE;
            uint64_t ad0 = MAKE_SMEM_DESC(sa);
            uint64_t bd0 = MAKE_SMEM_DESC(sa + MT_ * 128);
            #pragma unroll
            for (int s = 0; s < NSUB; s++) {
                uint32_t d = tmem + s * NMMA_;
                uint64_t ad = ad0 + s * 1024;
                #pragma unroll
                for (int ks = 0; ks < 2; ks++) {
                    mma_tc(d, ad + ks * 2,     bd0 + ks * 2,     idesc, (ci > 0 || ks > 0) ? 1u : 0u);
                    mma_tc(d, ad + 4 + ks * 2, bd0 + ks * 2,     idesc, 1u);
                    if (DT == 0)   // 3rd term only for bf16x3; fp16x2 drops hi*lo
                        mma_tc(d, ad + ks * 2, bd0 + 4 + ks * 2, idesc, 1u);
                }
            }
            TCGEN05_COMMIT(sbase + sc * 16 + 8);
        }
    }
    MBARRIER_WAIT_PARITY(sbase + ((nch - 1) % NST) * 16 + 8, ((nch - 1) / NST) & 1);
    TCGEN05_FENCE_AFTER();

    // ---------------- epilogue ----------------
    const int sub = wid >> 2;
    if (epi == 5) {
        int m = m0 + (wid & 3) * 32 + lane;
        #pragma unroll
        for (int jb = 0; jb < 2; jb++) {
            int cb = sub * 64 + jb * 32;
            uint32_t r1[32], r2[32];
            TCGEN05_LD_X32(r1, tmem + cb);
            TCGEN05_LD_X32(r2, tmem + 128 + cb);
            TCGEN05_WAIT_LD();
            #pragma unroll
            for (int q = 0; q < 8; q++) {
                int n = n0 + cb + q * 4;
                if (n < N) {
                    bf16 oh[4], ol[4];
                    #pragma unroll
                    for (int e = 0; e < 4; e++) {
                        float a = __uint_as_float(r1[q * 4 + e]);
                        float b = __uint_as_float(r2[q * 4 + e]);
                        float v = (a / (1.0f + expf(-a))) * b;
                        bf_split(v, oh[e], ol[e]);
                    }
                    *(uint2*)(Oh + (size_t)m * N + n) = *(uint2*)oh;
                    *(uint2*)(Ol + (size_t)m * N + n) = *(uint2*)ol;
                }
            }
        }
    } else {
        uint32_t tb;
        int m, c0, c1;
        if (MT_ == 256) { tb = tmem + sub * NMMA_; m = m0 + sub * 128 + (wid & 3) * 32 + lane; c0 = 0; c1 = NMMA_; }
        else            { tb = tmem; m = m0 + (wid & 3) * 32 + lane; c0 = sub * (NMMA_ / 2); c1 = c0 + NMMA_ / 2; }
        float* Crow = C + (size_t)m * N + n0;
        for (int cb = c0; cb < c1; cb += 32) {
            uint32_t r[32];
            TCGEN05_LD_X32(r, tb + cb);
            TCGEN05_WAIT_LD();
            #pragma unroll
            for (int q = 0; q < 8; q++) {
                int nrel = cb + q * 4;
                float4 v = make_float4(__uint_as_float(r[q * 4 + 0]), __uint_as_float(r[q * 4 + 1]),
                                       __uint_as_float(r[q * 4 + 2]), __uint_as_float(r[q * 4 + 3]));
                if (epi == 1) {
                    float4 hv = *(float4*)(Crow + nrel);
                    size_t xi = (size_t)m * DD + n0 + nrel;
                    __nv_bfloat162 xh0 = *(const __nv_bfloat162*)(auxh + xi);
                    __nv_bfloat162 xh1 = *(const __nv_bfloat162*)(auxh + xi + 2);
                    __nv_bfloat162 xl0 = *(const __nv_bfloat162*)(auxl + xi);
                    __nv_bfloat162 xl1 = *(const __nv_bfloat162*)(auxl + xi + 2);
                    float4 dv = *(const float4*)(aux0 + n0 + nrel);
                    v.x += hv.x + dv.x * (__bfloat162float(xh0.x) + __bfloat162float(xl0.x));
                    v.y += hv.y + dv.y * (__bfloat162float(xh0.y) + __bfloat162float(xl0.y));
                    v.z += hv.z + dv.z * (__bfloat162float(xh1.x) + __bfloat162float(xl1.x));
                    v.w += hv.w + dv.w * (__bfloat162float(xh1.y) + __bfloat162float(xl1.y));
                } else if (epi == 3) {
                    float4 hv = *(float4*)(Crow + nrel);
                    v.x += hv.x; v.y += hv.y; v.z += hv.z; v.w += hv.w;
                } else if (epi == 4) {
                    float4 bv = *(const float4*)(aux0 + n0 + nrel);
                    v.x += bv.x; v.y += bv.y; v.z += bv.z; v.w += bv.w;
                }
                *(float4*)(Crow + nrel) = v;
            }
        }
    }

    __syncthreads();
    if (tid == 0) {
        #pragma unroll
        for (int s = 0; s < NST; s++) { MBARRIER_INVAL(sbase + s * 16); MBARRIER_INVAL(sbase + s * 16 + 8); }
    }
    __syncthreads();
    if (wid == 0) TCGEN05_DEALLOC(tmem, TCOLS);
#else
    // -------- generic-arch fallback (correct, slow) --------
    const int tid = threadIdx.x;
    constexpr int OUT_TILE = SWIG_ ? 128 : NMMA_;
    const int m0 = blockIdx.x * MT_;
    const int n0 = blockIdx.y * OUT_TILE;
    auto ld = [](const bf16* p, size_t i) -> float {
        if (DT == 1) return __half2float(((const __half*)p)[i]);
        return __bfloat162float(p[i]);
    };
    for (int idx = tid; idx < MT_ * OUT_TILE; idx += 256) {
        int mi = m0 + idx / OUT_TILE;
        int n = n0 + idx % OUT_TILE;
        if (n >= N) continue;
        if (SWIG_) {
            float a = 0.f, b = 0.f;
            for (int k = 0; k < K; k++) {
                float av = ld(Ah, (size_t)mi * K + k) + ld(Al, (size_t)mi * K + k);
                a += av * (ld(Bh, (size_t)n * K + k) + ld(Bl, (size_t)n * K + k));
                b += av * (ld(B2h, (size_t)n * K + k) + ld(B2l, (size_t)n * K + k));
            }
            float v = (a / (1.0f + expf(-a))) * b;
            bf16 oh, ol; bf_split(v, oh, ol);
            Oh[(size_t)mi * N + n] = oh;
            Ol[(size_t)mi * N + n] = ol;
        } else {
            float acc = 0.f;
            for (int k = 0; k < K; k++) {
                float bv = ld(Bh, (size_t)n * K + k) + ((DT == 0) ? ld(Bl, (size_t)n * K + k) : 0.f);
                acc += (ld(Ah, (size_t)mi * K + k) + ld(Al, (size_t)mi * K + k)) * bv;
            }
            size_t ci = (size_t)mi * N + n;
            if (epi == 1)      acc += C[ci] + aux0[n] * (__bfloat162float(auxh[(size_t)mi * DD + n]) +
                                                         __bfloat162float(auxl[(size_t)mi * DD + n]));
            else if (epi == 3) acc += C[ci];
            else if (epi == 4) acc += aux0[n];
            C[ci] = acc;
        }
    }
#endif
}

// ---------------- fused split: weights -> hi/lo (head in fp16, rest bf16) ----------------
__global__ void split_all(const float* __restrict__ headW, const float* __restrict__ w1,
                          const float* __restrict__ w2, const float* __restrict__ w3,
                          const float* __restrict__ Bw, const float* __restrict__ Cw) {
    const long C0 = (long)VV * DD / 4;
    const long CW = (long)LLAYERS * DFFN * DD / 4;
    const long CB = (long)LLAYERS * SS * DD / 4;
    long j = (long)blockIdx.x * 256 + threadIdx.x;
    if (j < C0) {   // head weights: fp16 split
        float4 v = ((const float4*)headW)[j];
        __half h[4], l[4];
        fp16_split(v.x, h[0], l[0]);
        fp16_split(v.y, h[1], l[1]);
        fp16_split(v.z, h[2], l[2]);
        fp16_split(v.w, h[3], l[3]);
        ((uint2*)g_hwh)[j] = *(uint2*)h;
        ((uint2*)g_hwl)[j] = *(uint2*)l;
        return;
    }
    j -= C0;
    const float* src; bf16 *hi, *lo;
    if (j < CW)              { src = w1; hi = g_w1h; lo = g_w1l; }
    else if ((j -= CW) < CW) { src = w2; hi = g_w2h; lo = g_w2l; }
    else if ((j -= CW) < CW) { src = w3; hi = g_w3h; lo = g_w3l; }
    else if ((j -= CW) < CB) { src = Bw; hi = g_bwh; lo = g_bwl; }
    else if ((j -= CB) < CB) { src = Cw; hi = g_cwh; lo = g_cwl; }
    else return;
    float4 v = ((const float4*)src)[j];
    bf16 h[4], l[4];
    bf_split(v.x, h[0], l[0]);
    bf_split(v.y, h[1], l[1]);
    bf_split(v.z, h[2], l[2]);
    bf_split(v.w, h[3], l[3]);
    ((uint2*)hi)[j] = *(uint2*)h;
    ((uint2*)lo)[j] = *(uint2*)l;
}

// ---------------- embed ----------------
__global__ void embed_k(const int* __restrict__ x, const float* __restrict__ emb,
                        const float* __restrict__ pos, float* __restrict__ h) {
    int row = blockIdx.x;
    int t = row & (TT - 1);
    int tid = threadIdx.x;
    int v = x[row];
    float4 e = ((const float4*)(emb + (size_t)v * DD))[tid];
    float4 p = ((const float4*)(pos + (size_t)t * DD))[tid];
    ((float4*)(h + (size_t)row * DD))[tid] =
        make_float4(e.x + p.x, e.y + p.y, e.z + p.z, e.w + p.w);
}

// ---------------- layernorm D=512 -> split hi/lo (bf16, or fp16 when hmode=1) ----------------
__global__ void ln512(const float* __restrict__ X, bf16* __restrict__ Yh, bf16* __restrict__ Yl,
                      const float* __restrict__ w, const float* __restrict__ bvec, int hmode) {
    int row = blockIdx.x;
    int tid = threadIdx.x;
    float4 v = ((const float4*)(X + (size_t)row * DD))[tid];
    float sum = v.x + v.y + v.z + v.w;
    float sq  = v.x * v.x + v.y * v.y + v.z * v.z + v.w * v.w;
    #pragma unroll
    for (int o = 16; o > 0; o >>= 1) {
        sum += __shfl_xor_sync(0xffffffffu, sum, o);
        sq  += __shfl_xor_sync(0xffffffffu, sq, o);
    }
    __shared__ float s1[4], s2[4];
    if ((tid & 31) == 0) { s1[tid >> 5] = sum; s2[tid >> 5] = sq; }
    __syncthreads();
    sum = s1[0] + s1[1] + s1[2] + s1[3];
    sq  = s2[0] + s2[1] + s2[2] + s2[3];
    float mu = sum * (1.0f / DD);
    float var = sq * (1.0f / DD) - mu * mu;
    float rs = rsqrtf(var + 1e-5f);
    float4 wv = ((const float4*)w)[tid];
    float4 bv = ((const float4*)bvec)[tid];
    float o[4];
    o[0] = (v.x - mu) * rs * wv.x + bv.x;
    o[1] = (v.y - mu) * rs * wv.y + bv.y;
    o[2] = (v.z - mu) * rs * wv.z + bv.z;
    o[3] = (v.w - mu) * rs * wv.w + bv.w;
    if (hmode) {
        __half h[4], l[4];
        #pragma unroll
        for (int e = 0; e < 4; e++) fp16_split(o[e], h[e], l[e]);
        *(uint2*)((__half*)Yh + (size_t)row * DD + tid * 4) = *(uint2*)h;
        *(uint2*)((__half*)Yl + (size_t)row * DD + tid * 4) = *(uint2*)l;
    } else {
        bf16 h[4], l[4];
        #pragma unroll
        for (int e = 0; e < 4; e++) bf_split(o[e], h[e], l[e]);
        *(uint2*)(Yh + (size_t)row * DD + tid * 4) = *(uint2*)h;
        *(uint2*)(Yl + (size_t)row * DD + tid * 4) = *(uint2*)l;
    }
}

// ---------------- SSM scan -> bf16 hi/lo ----------------
__global__ void ssm_scan(const float* __restrict__ Bu, bf16* __restrict__ Hh,
                         bf16* __restrict__ Hl, const float* __restrict__ loglam) {
    const int SEG = TT / 128;     // 16
    int b  = blockIdx.x >> 5;
    int cg = blockIdx.x & 31;
    int sx = threadIdx.x;         // 0..7
    int sy = threadIdx.y;         // 0..127
    int s = cg * 8 + sx;
    float lam = 1.0f / (1.0f + expf(-loglam[s]));
    size_t base = ((size_t)(b * TT + sy * SEG)) * SS + s;

    float h = 0.0f;
    #pragma unroll
    for (int i = 0; i < SEG; i++) h = lam * h + Bu[base + (size_t)i * SS];

    __shared__ float carry[128][9];
    __shared__ float cin[128][9];
    carry[sy][sx] = h;
    __syncthreads();
    if (sy == 0) {
        float lamS = lam;
        #pragma unroll
        for (int q = 0; q < 4; q++) lamS *= lamS;     // lam^16
        float c = 0.0f;
        for (int j = 0; j < 128; j++) { cin[j][sx] = c; c = lamS * c + carry[j][sx]; }
    }
    __syncthreads();

    h = cin[sy][sx];
    #pragma unroll
    for (int i = 0; i < SEG; i++) {
        size_t idx = base + (size_t)i * SS;
        h = lam * h + Bu[idx];
        bf16 hb, lb;
        bf_split(h, hb, lb);
        Hh[idx] = hb;
        Hl[idx] = lb;
    }
}

// ---------------- launch ----------------
#define SM_SMALL (1024 + 4 * (192 * 128))   // MT=128, NT=64, NST=4
#define SM_SWIG  (1024 + 2 * (384 * 128))   // MT=128, NT=256, NST=2
#define SM_HEAD  (1024 + 2 * (384 * 128))   // MT=128, NT=256, NST=2

extern "C" void kernel_launch(void* const* d_in, const int* in_sizes, int n_in,
                              void* d_out, int out_size) {
    const int*   x      = (const int*)  d_in[0];
    const float* emb    = (const float*)d_in[1];
    const float* pos    = (const float*)d_in[2];
    const float* loglam = (const float*)d_in[3];
    const float* Bw     = (const float*)d_in[4];
    const float* Cw     = (const float*)d_in[5];
    const float* Dp     = (const float*)d_in[6];
    const float* n1w    = (const float*)d_in[7];
    const float* n1b    = (const float*)d_in[8];
    const float* n2w    = (const float*)d_in[9];
    const float* n2b    = (const float*)d_in[10];
    const float* w1     = (const float*)d_in[11];
    const float* w2     = (const float*)d_in[12];
    const float* w3     = (const float*)d_in[13];
    const float* now    = (const float*)d_in[14];
    const float* nob    = (const float*)d_in[15];
    const float* headW  = (const float*)d_in[16];
    const float* headb  = (const float*)d_in[17];
    float* out = (float*)d_out;

    float *h, *bu;
    bf16 *xnh, *xnl, *buh, *bul, *glh, *gll;
    bf16 *w1h, *w1l, *w2h, *w2l, *w3h, *w3l, *bwh, *bwl, *cwh, *cwl;
    __half *hwh, *hwl;
    cudaGetSymbolAddress((void**)&h,   g_h);
    cudaGetSymbolAddress((void**)&xnh, g_xnh);
    cudaGetSymbolAddress((void**)&xnl, g_xnl);
    cudaGetSymbolAddress((void**)&bu,  g_bu);
    cudaGetSymbolAddress((void**)&buh, g_buh);
    cudaGetSymbolAddress((void**)&bul, g_bul);
    cudaGetSymbolAddress((void**)&glh, g_glh);
    cudaGetSymbolAddress((void**)&gll, g_gll);
    cudaGetSymbolAddress((void**)&w1h, g_w1h);
    cudaGetSymbolAddress((void**)&w1l, g_w1l);
    cudaGetSymbolAddress((void**)&w2h, g_w2h);
    cudaGetSymbolAddress((void**)&w2l, g_w2l);
    cudaGetSymbolAddress((void**)&w3h, g_w3h);
    cudaGetSymbolAddress((void**)&w3l, g_w3l);
    cudaGetSymbolAddress((void**)&bwh, g_bwh);
    cudaGetSymbolAddress((void**)&bwl, g_bwl);
    cudaGetSymbolAddress((void**)&cwh, g_cwh);
    cudaGetSymbolAddress((void**)&cwl, g_cwl);
    cudaGetSymbolAddress((void**)&hwh, g_hwh);
    cudaGetSymbolAddress((void**)&hwl, g_hwl);

    cudaFuncSetAttribute((const void*)gemm3x<128, 64, false, 4, 0>,
                         cudaFuncAttributeMaxDynamicSharedMemorySize, SM_SMALL);
    cudaFuncSetAttribute((const void*)gemm3x<128, 256, true, 2, 0>,
                         cudaFuncAttributeMaxDynamicSharedMemorySize, SM_SWIG);
    cudaFuncSetAttribute((const void*)gemm3x<128, 256, false, 2, 1>,
                         cudaFuncAttributeMaxDynamicSharedMemorySize, SM_HEAD);

    // one fused split launch
    {
        long total = (long)VV * DD / 4 + 3L * LLAYERS * DFFN * DD / 4 + 2L * LLAYERS * SS * DD / 4;
        split_all<<<(unsigned)((total + 255) / 256), 256>>>(headW, w1, w2, w3, Bw, Cw);
    }

    embed_k<<<BT, 128>>>(x, emb, pos, h);

    for (int l = 0; l < LLAYERS; l++) {
        ln512<<<BT, 128>>>(h, xnh, xnl, n1w + l * DD, n1b + l * DD, 0);
        // Bu = xn @ Bw^T   [4096,256]
        gemm3x<128, 64, false, 4, 0><<<dim3(32, 4), 256, SM_SMALL>>>(
            xnh, xnl, bwh + (size_t)l * SS * DD, bwl + (size_t)l * SS * DD,
            nullptr, nullptr, bu, nullptr, nullptr, SS, DD, 0, nullptr, nullptr, nullptr);
        ssm_scan<<<64, dim3(8, 128)>>>(bu, buh, bul, loglam + l * SS);
        // h += hscan @ Cw^T + Dp*xn   [4096,512]
        gemm3x<128, 64, false, 4, 0><<<dim3(32, 8), 256, SM_SMALL>>>(
            buh, bul, cwh + (size_t)l * DD * SS, cwl + (size_t)l * DD * SS,
            nullptr, nullptr, h, nullptr, nullptr, DD, SS, 1, Dp + l * DD, xnh, xnl);
        ln512<<<BT, 128>>>(h, xnh, xnl, n2w + l * DD, n2b + l * DD, 0);
        // gl = silu(xn@w1^T)*(xn@w2^T)   [4096,1368]
        gemm3x<128, 256, true, 2, 0><<<dim3(32, 11), 256, SM_SWIG>>>(
            xnh, xnl, w1h + (size_t)l * DFFN * DD, w1l + (size_t)l * DFFN * DD,
            w2h + (size_t)l * DFFN * DD, w2l + (size_t)l * DFFN * DD,
            nullptr, glh, gll, DFFN, DD, 5, nullptr, nullptr, nullptr);
        // h += gl @ w3^T   [4096,512]
        gemm3x<128, 64, false, 4, 0><<<dim3(32, 8), 256, SM_SMALL>>>(
            glh, gll, w3h + (size_t)l * DD * DFFN, w3l + (size_t)l * DD * DFFN,
            nullptr, nullptr, h, nullptr, nullptr, DD, DFFN, 3, nullptr, nullptr, nullptr);
    }

    // final LN -> fp16 hi/lo (head path)
    ln512<<<BT, 128>>>(h, xnh, xnl, now, nob, 1);
    // logits = xn @ headW^T + headb   [4096,32000]  — fp16 2-term, B-lo loads skipped
    gemm3x<128, 256, false, 2, 1><<<dim3(32, 125), 256, SM_HEAD>>>(
        xnh, xnl, (bf16*)hwh, (bf16*)hwl, nullptr, nullptr, out, nullptr, nullptr,
        VV, DD, 4, headb, nullptr, nullptr);
}

// round 15
// speedup vs baseline: 1.5581x; 1.0045x over previous
#include <cuda_runtime.h>
#include <cuda_bf16.h>
#include <cuda_fp16.h>
#include <cstdint>
#include <math.h>

#define BT 4096
#define TT 2048
#define DD 512
#define SS 256
#define LLAYERS 4
#define DFFN 1368
#define VV 32000

#if defined(__CUDA_ARCH__) && defined(__CUDA_ARCH_FEAT_SM103_ALL)
#define HAS_TCG 1
#else
#define HAS_TCG 0
#endif

typedef __nv_bfloat16 bf16;

// ---------------- scratch ----------------
__device__ float g_h[BT * DD];
__device__ __align__(16) bf16 g_xnh[BT * DD];   // bf16 pairs (layers) or fp16 bits (final LN)
__device__ __align__(16) bf16 g_xnl[BT * DD];
__device__ float g_bu[BT * SS];
__device__ __align__(16) bf16 g_buh[BT * SS];
__device__ __align__(16) bf16 g_bul[BT * SS];
__device__ __align__(16) bf16 g_glh[(size_t)BT * DFFN];
__device__ __align__(16) bf16 g_gll[(size_t)BT * DFFN];
__device__ __align__(16) bf16 g_w1h[(size_t)LLAYERS * DFFN * DD];
__device__ __align__(16) bf16 g_w1l[(size_t)LLAYERS * DFFN * DD];
__device__ __align__(16) bf16 g_w2h[(size_t)LLAYERS * DFFN * DD];
__device__ __align__(16) bf16 g_w2l[(size_t)LLAYERS * DFFN * DD];
__device__ __align__(16) bf16 g_w3h[(size_t)LLAYERS * DD * DFFN];
__device__ __align__(16) bf16 g_w3l[(size_t)LLAYERS * DD * DFFN];
__device__ __align__(16) bf16 g_bwh[LLAYERS * SS * DD];
__device__ __align__(16) bf16 g_bwl[LLAYERS * SS * DD];
__device__ __align__(16) bf16 g_cwh[LLAYERS * DD * SS];
__device__ __align__(16) bf16 g_cwl[LLAYERS * DD * SS];
__device__ __align__(16) __half g_hwh[(size_t)VV * DD];   // head weights: fp16 split
__device__ __align__(16) __half g_hwl[(size_t)VV * DD];

// ---------------- helpers ----------------
__device__ __forceinline__ uint32_t smem_u32(const void* p) {
    uint32_t a;
    asm("{ .reg .u64 t; cvta.to.shared.u64 t, %1; cvt.u32.u64 %0, t; }" : "=r"(a) : "l"(p));
    return a;
}
__device__ __forceinline__ void bf_split(float x, bf16& hi, bf16& lo) {
    hi = __float2bfloat16_rn(x);
    lo = __float2bfloat16_rn(x - __bfloat162float(hi));
}
__device__ __forceinline__ void fp16_split(float x, __half& hi, __half& lo) {
    hi = __float2half_rn(x);
    lo = __float2half_rn(x - __half2float(hi));
}
#define SWZ(o) ((o) ^ (((o) >> 3) & 0x70))

#if HAS_TCG
__device__ __forceinline__ uint32_t elect_one() {
    uint32_t r;
    asm volatile("{ .reg .pred p; elect.sync _|p, 0xFFFFFFFF; selp.b32 %0, 1, 0, p; }" : "=r"(r));
    return r;
}
static constexpr uint64_t DESC_BASE_SW128 =
    (uint64_t(2) << 61) | (uint64_t(1) << 46) | (uint64_t(64) << 32) | (uint64_t(1) << 16);
#define MAKE_SMEM_DESC(addr) (DESC_BASE_SW128 | ((uint64_t)((addr) >> 4) & 0x3FFF))

#define MBARRIER_INIT(mbar, cnt) \
    asm volatile("mbarrier.init.shared.b64 [%0], %1;" :: "r"((uint32_t)(mbar)), "r"((uint32_t)(cnt)) : "memory")
#define MBARRIER_INVAL(mbar) \
    asm volatile("mbarrier.inval.shared.b64 [%0];" :: "r"((uint32_t)(mbar)) : "memory")
#define MBARRIER_WAIT_PARITY(mbar_a, par) do { \
    uint32_t _m = (uint32_t)(mbar_a); uint32_t _p = (uint32_t)(par); uint32_t _d; \
    asm volatile("{ .reg .pred p; mbarrier.try_wait.parity.acquire.cta.shared::cta.b64 p, [%1], %2; selp.b32 %0, 1, 0, p; }" \
        : "=r"(_d) : "r"(_m), "r"(_p) : "memory"); \
    if (!_d) { \
        asm volatile("{ .reg .pred P1; WL_%=: mbarrier.try_wait.parity.acquire.cta.shared::cta.b64 P1, [%0], %1, 0x989680; @P1 bra.uni WD_%=; bra.uni WL_%=; WD_%=: }" \
            :: "r"(_m), "r"(_p) : "memory"); \
    } } while (0)

// .noinc is load-bearing: barrier init count = 256 (one arrive/thread/phase).
#define CPASYNC_ARRIVE(mbar) \
    asm volatile("cp.async.mbarrier.arrive.noinc.shared::cta.b64 [%0];" :: "r"((uint32_t)(mbar)) : "memory")

#define TCGEN05_ALLOC(slot, n) \
    asm volatile("tcgen05.alloc.cta_group::1.sync.aligned.shared::cta.b32 [%0], %1;" :: "r"((uint32_t)(slot)), "r"((uint32_t)(n)) : "memory")
#define TCGEN05_DEALLOC(t, n) \
    asm volatile("tcgen05.dealloc.cta_group::1.sync.aligned.b32 %0, %1;" :: "r"(t), "r"((uint32_t)(n)))
#define TCGEN05_RELINQ() \
    asm volatile("tcgen05.relinquish_alloc_permit.cta_group::1.sync.aligned;")
#define TCGEN05_COMMIT(mbar) \
    asm volatile("tcgen05.commit.cta_group::1.mbarrier::arrive::one.shared::cluster.b64 [%0];" :: "r"((uint32_t)(mbar)) : "memory")
#define TCGEN05_FENCE_AFTER() asm volatile("tcgen05.fence::after_thread_sync;" ::: "memory")
#define TCGEN05_WAIT_LD() asm volatile("tcgen05.wait::ld.sync.aligned;" ::: "memory")

#define TCGEN05_LD_X32(r, addr) \
    asm volatile("tcgen05.ld.sync.aligned.32x32b.x32.b32 {%0,%1,%2,%3,%4,%5,%6,%7,%8,%9,%10,%11,%12,%13,%14,%15,%16,%17,%18,%19,%20,%21,%22,%23,%24,%25,%26,%27,%28,%29,%30,%31}, [%32];" \
        : "=r"((r)[0]),"=r"((r)[1]),"=r"((r)[2]),"=r"((r)[3]),"=r"((r)[4]),"=r"((r)[5]),"=r"((r)[6]),"=r"((r)[7]), \
          "=r"((r)[8]),"=r"((r)[9]),"=r"((r)[10]),"=r"((r)[11]),"=r"((r)[12]),"=r"((r)[13]),"=r"((r)[14]),"=r"((r)[15]), \
          "=r"((r)[16]),"=r"((r)[17]),"=r"((r)[18]),"=r"((r)[19]),"=r"((r)[20]),"=r"((r)[21]),"=r"((r)[22]),"=r"((r)[23]), \
          "=r"((r)[24]),"=r"((r)[25]),"=r"((r)[26]),"=r"((r)[27]),"=r"((r)[28]),"=r"((r)[29]),"=r"((r)[30]),"=r"((r)[31]) \
        : "r"(addr))

__device__ __forceinline__ void mma_tc(uint32_t d, uint64_t ad, uint64_t bd,
                                       uint32_t idesc, uint32_t en) {
    asm volatile(
        "{ .reg .pred p; setp.ne.u32 p, %4, 0;\n\t"
        "tcgen05.mma.cta_group::1.kind::f16 [%0], %1, %2, %3, {%5, %5, %5, %5}, p; }"
        :: "r"(d), "l"(ad), "l"(bd), "r"(idesc), "r"(en), "r"(0u)
        : "memory");
}
#endif  // HAS_TCG

// ============ 3-term (bf16, DT=0) / 2-term (fp16, DT=1) compensated GEMM ============
// C[M,N] = A[M,K] @ B[N,K]^T; A,B pre-split hi/lo, SMEM row 128B = [hi 32 | lo 32] elems.
// EPI is compile-time so each instantiation's epilogue codegen is isolated:
//   0: C=acc; 1: C += acc + aux0[n]*(auxh+auxl); 3: C += acc;
//   4: C = acc + aux0[n] with evict-first (.cs) streaming stores (head);
//   5: swiglu -> Oh/Ol bf16-split outputs.
template<int MT_, int NMMA_, bool SWIG_, int NST, int DT, int EPI>
__global__ __launch_bounds__(256, 2) void gemm3x(
    const bf16* __restrict__ Ah, const bf16* __restrict__ Al,
    const bf16* __restrict__ Bh, const bf16* __restrict__ Bl,
    const bf16* __restrict__ B2h, const bf16* __restrict__ B2l,
    float* __restrict__ C, bf16* __restrict__ Oh, bf16* __restrict__ Ol,
    int N, int K,
    const float* __restrict__ aux0, const bf16* __restrict__ auxh, const bf16* __restrict__ auxl)
{
#if HAS_TCG
    constexpr int NTB  = SWIG_ ? 256 : NMMA_;
    constexpr int ROWS = MT_ + NTB;
    constexpr int STAGE = ROWS * 128;
    constexpr int NSUB = MT_ / 128;
    constexpr int TCOLS = (NSUB * NMMA_) < 128 ? 128 : (NSUB * NMMA_);
    constexpr int NSEG = ROWS * 8 / 256;
    constexpr int OUT_TILE = SWIG_ ? 128 : NMMA_;
    constexpr uint32_t TYB = (DT == 1) ? 0u : 1u;   // atype/btype: f16=0, bf16=1
    const uint32_t idesc = (1u << 4) | (TYB << 7) | (TYB << 10) | ((NMMA_ / 8) << 17) | (8u << 24);

    extern __shared__ char smem[];
    const uint32_t sbase = smem_u32(smem);
    const int tid = threadIdx.x;
    const int wid = tid >> 5;
    const int lane = tid & 31;
    const int m0 = blockIdx.x * MT_;
    const int n0 = blockIdx.y * OUT_TILE;

    if (tid == 0) {
        #pragma unroll
        for (int s = 0; s < NST; s++) {
            MBARRIER_INIT(sbase + s * 16, 256);
            MBARRIER_INIT(sbase + s * 16 + 8, 1);
        }
    }
    if (wid == 0) { TCGEN05_ALLOC(sbase + 64, TCOLS); TCGEN05_RELINQ(); }
    __syncthreads();
    uint32_t tmem;
    asm volatile("ld.shared.b32 %0, [%1];" : "=r"(tmem) : "r"(sbase + 64));

    // per-thread loader state
    const bf16* gp[NSEG];
    uint32_t so[NSEG];
    int koff[NSEG];
    bool nok[NSEG];
    #pragma unroll
    for (int i = 0; i < NSEG; i++) {
        int f = i * 256 + tid;
        int row = f >> 3, s8 = f & 7;
        int half = s8 >> 2, q = s8 & 3;
        koff[i] = q * 8;
        so[i] = SWZ(row * 128 + half * 64 + q * 16);
        if (row < MT_) {
            gp[i] = (half ? Al : Ah) + (size_t)(m0 + row) * K + q * 8;
            nok[i] = true;
        } else {
            int r2 = row - MT_;
            int n;
            const bf16* ph;
            if (SWIG_ && r2 >= 128) { n = n0 + r2 - 128; ph = half ? B2l : B2h; }
            else                    { n = n0 + r2;       ph = half ? Bl  : Bh; }
            nok[i] = (n < N);
            if (DT == 1 && half == 1) nok[i] = false;   // B-lo unused in fp16x2 -> zero-fill
            if (n >= N) n = 0;
            gp[i] = ph + (size_t)n * K + q * 8;
        }
    }

    const int nch = (K + 31) / 32;

    auto cp_chunk = [&](int c, int st) {
        int k0 = c * 32;
        uint32_t sb2 = sbase + 1024 + st * STAGE;
        #pragma unroll
        for (int i = 0; i < NSEG; i++) {
            uint32_t sz = (nok[i] && (k0 + koff[i]) < K) ? 16u : 0u;   // sz=0 -> zero-fill
            asm volatile("cp.async.cg.shared.global [%0], [%1], 16, %2;"
                         :: "r"(sb2 + so[i]), "l"(gp[i] + k0), "r"(sz));
        }
    };

    #pragma unroll
    for (int p = 0; p < NST - 1; p++) {
        if (p < nch) { cp_chunk(p, p); CPASYNC_ARRIVE(sbase + p * 16); }
    }

    for (int ci = 0; ci < nch; ci++) {
        int sc = ci % NST;
        int nxt = ci + NST - 1;
        if (nxt < nch) {
            int sn = nxt % NST;
            if (nxt >= NST)
                MBARRIER_WAIT_PARITY(sbase + sn * 16 + 8, ((nxt / NST) + 1) & 1);
            cp_chunk(nxt, sn);
            CPASYNC_ARRIVE(sbase + sn * 16);
        }
        if (wid == 0 && elect_one()) {
            MBARRIER_WAIT_PARITY(sbase + sc * 16, (ci / NST) & 1);
            asm volatile("fence.proxy.async.shared::cta;" ::: "memory");
            uint32_t sa = sbase + 1024 + sc * STAGE;
            uint64_t ad0 = MAKE_SMEM_DESC(sa);
            uint64_t bd0 = MAKE_SMEM_DESC(sa + MT_ * 128);
            #pragma unroll
            for (int s = 0; s < NSUB; s++) {
                uint32_t d = tmem + s * NMMA_;
                uint64_t ad = ad0 + s * 1024;
                #pragma unroll
                for (int ks = 0; ks < 2; ks++) {
                    mma_tc(d, ad + ks * 2,     bd0 + ks * 2,     idesc, (ci > 0 || ks > 0) ? 1u : 0u);
                    mma_tc(d, ad + 4 + ks * 2, bd0 + ks * 2,     idesc, 1u);
                    if (DT == 0)   // 3rd term only for bf16x3; fp16x2 drops hi*lo
                        mma_tc(d, ad + ks * 2, bd0 + 4 + ks * 2, idesc, 1u);
                }
            }
            TCGEN05_COMMIT(sbase + sc * 16 + 8);
        }
    }
    MBARRIER_WAIT_PARITY(sbase + ((nch - 1) % NST) * 16 + 8, ((nch - 1) / NST) & 1);
    TCGEN05_FENCE_AFTER();

    // ---------------- epilogue (compile-time selected) ----------------
    const int sub = wid >> 2;
    if (EPI == 5) {
        int m = m0 + (wid & 3) * 32 + lane;
        #pragma unroll
        for (int jb = 0; jb < 2; jb++) {
            int cb = sub * 64 + jb * 32;
            uint32_t r1[32], r2[32];
            TCGEN05_LD_X32(r1, tmem + cb);
            TCGEN05_LD_X32(r2, tmem + 128 + cb);
            TCGEN05_WAIT_LD();
            #pragma unroll
            for (int q = 0; q < 8; q++) {
                int n = n0 + cb + q * 4;
                if (n < N) {
                    bf16 oh[4], ol[4];
                    #pragma unroll
                    for (int e = 0; e < 4; e++) {
                        float a = __uint_as_float(r1[q * 4 + e]);
                        float b = __uint_as_float(r2[q * 4 + e]);
                        float v = (a / (1.0f + expf(-a))) * b;
                        bf_split(v, oh[e], ol[e]);
                    }
                    *(uint2*)(Oh + (size_t)m * N + n) = *(uint2*)oh;
                    *(uint2*)(Ol + (size_t)m * N + n) = *(uint2*)ol;
                }
            }
        }
    } else {
        uint32_t tb;
        int m, c0, c1;
        if (MT_ == 256) { tb = tmem + sub * NMMA_; m = m0 + sub * 128 + (wid & 3) * 32 + lane; c0 = 0; c1 = NMMA_; }
        else            { tb = tmem; m = m0 + (wid & 3) * 32 + lane; c0 = sub * (NMMA_ / 2); c1 = c0 + NMMA_ / 2; }
        float* Crow = C + (size_t)m * N + n0;
        for (int cb = c0; cb < c1; cb += 32) {
            uint32_t r[32];
            TCGEN05_LD_X32(r, tb + cb);
            TCGEN05_WAIT_LD();
            #pragma unroll
            for (int q = 0; q < 8; q++) {
                int nrel = cb + q * 4;
                float4 v = make_float4(__uint_as_float(r[q * 4 + 0]), __uint_as_float(r[q * 4 + 1]),
                                       __uint_as_float(r[q * 4 + 2]), __uint_as_float(r[q * 4 + 3]));
                if (EPI == 1) {
                    float4 hv = *(float4*)(Crow + nrel);
                    size_t xi = (size_t)m * DD + n0 + nrel;
                    __nv_bfloat162 xh0 = *(const __nv_bfloat162*)(auxh + xi);
                    __nv_bfloat162 xh1 = *(const __nv_bfloat162*)(auxh + xi + 2);
                    __nv_bfloat162 xl0 = *(const __nv_bfloat162*)(auxl + xi);
                    __nv_bfloat162 xl1 = *(const __nv_bfloat162*)(auxl + xi + 2);
                    float4 dv = *(const float4*)(aux0 + n0 + nrel);
                    v.x += hv.x + dv.x * (__bfloat162float(xh0.x) + __bfloat162float(xl0.x));
                    v.y += hv.y + dv.y * (__bfloat162float(xh0.y) + __bfloat162float(xl0.y));
                    v.z += hv.z + dv.z * (__bfloat162float(xh1.x) + __bfloat162float(xl1.x));
                    v.w += hv.w + dv.w * (__bfloat162float(xh1.y) + __bfloat162float(xl1.y));
                    *(float4*)(Crow + nrel) = v;
                } else if (EPI == 3) {
                    float4 hv = *(float4*)(Crow + nrel);
                    v.x += hv.x; v.y += hv.y; v.z += hv.z; v.w += hv.w;
                    *(float4*)(Crow + nrel) = v;
                } else if (EPI == 4) {
                    float4 bv = *(const float4*)(aux0 + n0 + nrel);
                    v.x += bv.x; v.y += bv.y; v.z += bv.z; v.w += bv.w;
                    // evict-first streaming store: logits must not thrash L2 (headW/A residency)
                    asm volatile("st.global.cs.v4.f32 [%0], {%1, %2, %3, %4};"
                                 :: "l"(Crow + nrel), "f"(v.x), "f"(v.y), "f"(v.z), "f"(v.w)
                                 : "memory");
                } else {
                    *(float4*)(Crow + nrel) = v;
                }
            }
        }
    }

    __syncthreads();
    if (tid == 0) {
        #pragma unroll
        for (int s = 0; s < NST; s++) { MBARRIER_INVAL(sbase + s * 16); MBARRIER_INVAL(sbase + s * 16 + 8); }
    }
    __syncthreads();
    if (wid == 0) TCGEN05_DEALLOC(tmem, TCOLS);
#else
    // -------- generic-arch fallback (correct, slow) --------
    const int tid = threadIdx.x;
    constexpr int OUT_TILE = SWIG_ ? 128 : NMMA_;
    const int m0 = blockIdx.x * MT_;
    const int n0 = blockIdx.y * OUT_TILE;
    auto ld = [](const bf16* p, size_t i) -> float {
        if (DT == 1) return __half2float(((const __half*)p)[i]);
        return __bfloat162float(p[i]);
    };
    for (int idx = tid; idx < MT_ * OUT_TILE; idx += 256) {
        int mi = m0 + idx / OUT_TILE;
        int n = n0 + idx % OUT_TILE;
        if (n >= N) continue;
        if (SWIG_) {
            float a = 0.f, b = 0.f;
            for (int k = 0; k < K; k++) {
                float av = ld(Ah, (size_t)mi * K + k) + ld(Al, (size_t)mi * K + k);
                a += av * (ld(Bh, (size_t)n * K + k) + ld(Bl, (size_t)n * K + k));
                b += av * (ld(B2h, (size_t)n * K + k) + ld(B2l, (size_t)n * K + k));
            }
            float v = (a / (1.0f + expf(-a))) * b;
            bf16 oh, ol; bf_split(v, oh, ol);
            Oh[(size_t)mi * N + n] = oh;
            Ol[(size_t)mi * N + n] = ol;
        } else {
            float acc = 0.f;
            for (int k = 0; k < K; k++) {
                float bv = ld(Bh, (size_t)n * K + k) + ((DT == 0) ? ld(Bl, (size_t)n * K + k) : 0.f);
                acc += (ld(Ah, (size_t)mi * K + k) + ld(Al, (size_t)mi * K + k)) * bv;
            }
            size_t ci = (size_t)mi * N + n;
            if (EPI == 1)      acc += C[ci] + aux0[n] * (__bfloat162float(auxh[(size_t)mi * DD + n]) +
                                                         __bfloat162float(auxl[(size_t)mi * DD + n]));
            else if (EPI == 3) acc += C[ci];
            else if (EPI == 4) acc += aux0[n];
            C[ci] = acc;
        }
    }
#endif
}

// ---------------- fused split: weights -> hi/lo (head in fp16, rest bf16) ----------------
__global__ void split_all(const float* __restrict__ headW, const float* __restrict__ w1,
                          const float* __restrict__ w2, const float* __restrict__ w3,
                          const float* __restrict__ Bw, const float* __restrict__ Cw) {
    const long C0 = (long)VV * DD / 4;
    const long CW = (long)LLAYERS * DFFN * DD / 4;
    const long CB = (long)LLAYERS * SS * DD / 4;
    long j = (long)blockIdx.x * 256 + threadIdx.x;
    if (j < C0) {   // head weights: fp16 split
        float4 v = ((const float4*)headW)[j];
        __half h[4], l[4];
        fp16_split(v.x, h[0], l[0]);
        fp16_split(v.y, h[1], l[1]);
        fp16_split(v.z, h[2], l[2]);
        fp16_split(v.w, h[3], l[3]);
        ((uint2*)g_hwh)[j] = *(uint2*)h;
        ((uint2*)g_hwl)[j] = *(uint2*)l;
        return;
    }
    j -= C0;
    const float* src; bf16 *hi, *lo;
    if (j < CW)              { src = w1; hi = g_w1h; lo = g_w1l; }
    else if ((j -= CW) < CW) { src = w2; hi = g_w2h; lo = g_w2l; }
    else if ((j -= CW) < CW) { src = w3; hi = g_w3h; lo = g_w3l; }
    else if ((j -= CW) < CB) { src = Bw; hi = g_bwh; lo = g_bwl; }
    else if ((j -= CB) < CB) { src = Cw; hi = g_cwh; lo = g_cwl; }
    else return;
    float4 v = ((const float4*)src)[j];
    bf16 h[4], l[4];
    bf_split(v.x, h[0], l[0]);
    bf_split(v.y, h[1], l[1]);
    bf_split(v.z, h[2], l[2]);
    bf_split(v.w, h[3], l[3]);
    ((uint2*)hi)[j] = *(uint2*)h;
    ((uint2*)lo)[j] = *(uint2*)l;
}

// ---------------- embed ----------------
__global__ void embed_k(const int* __restrict__ x, const float* __restrict__ emb,
                        const float* __restrict__ pos, float* __restrict__ h) {
    int row = blockIdx.x;
    int t = row & (TT - 1);
    int tid = threadIdx.x;
    int v = x[row];
    float4 e = ((const float4*)(emb + (size_t)v * DD))[tid];
    float4 p = ((const float4*)(pos + (size_t)t * DD))[tid];
    ((float4*)(h + (size_t)row * DD))[tid] =
        make_float4(e.x + p.x, e.y + p.y, e.z + p.z, e.w + p.w);
}

// ---------------- layernorm D=512 -> split hi/lo (bf16, or fp16 when hmode=1) ----------------
__global__ void ln512(const float* __restrict__ X, bf16* __restrict__ Yh, bf16* __restrict__ Yl,
                      const float* __restrict__ w, const float* __restrict__ bvec, int hmode) {
    int row = blockIdx.x;
    int tid = threadIdx.x;
    float4 v = ((const float4*)(X + (size_t)row * DD))[tid];
    float sum = v.x + v.y + v.z + v.w;
    float sq  = v.x * v.x + v.y * v.y + v.z * v.z + v.w * v.w;
    #pragma unroll
    for (int o = 16; o > 0; o >>= 1) {
        sum += __shfl_xor_sync(0xffffffffu, sum, o);
        sq  += __shfl_xor_sync(0xffffffffu, sq, o);
    }
    __shared__ float s1[4], s2[4];
    if ((tid & 31) == 0) { s1[tid >> 5] = sum; s2[tid >> 5] = sq; }
    __syncthreads();
    sum = s1[0] + s1[1] + s1[2] + s1[3];
    sq  = s2[0] + s2[1] + s2[2] + s2[3];
    float mu = sum * (1.0f / DD);
    float var = sq * (1.0f / DD) - mu * mu;
    float rs = rsqrtf(var + 1e-5f);
    float4 wv = ((const float4*)w)[tid];
    float4 bv = ((const float4*)bvec)[tid];
    float o[4];
    o[0] = (v.x - mu) * rs * wv.x + bv.x;
    o[1] = (v.y - mu) * rs * wv.y + bv.y;
    o[2] = (v.z - mu) * rs * wv.z + bv.z;
    o[3] = (v.w - mu) * rs * wv.w + bv.w;
    if (hmode) {
        __half h[4], l[4];
        #pragma unroll
        for (int e = 0; e < 4; e++) fp16_split(o[e], h[e], l[e]);
        *(uint2*)((__half*)Yh + (size_t)row * DD + tid * 4) = *(uint2*)h;
        *(uint2*)((__half*)Yl + (size_t)row * DD + tid * 4) = *(uint2*)l;
    } else {
        bf16 h[4], l[4];
        #pragma unroll
        for (int e = 0; e < 4; e++) bf_split(o[e], h[e], l[e]);
        *(uint2*)(Yh + (size_t)row * DD + tid * 4) = *(uint2*)h;
        *(uint2*)(Yl + (size_t)row * DD + tid * 4) = *(uint2*)l;
    }
}

// ---------------- SSM scan -> bf16 hi/lo ----------------
__global__ void ssm_scan(const float* __restrict__ Bu, bf16* __restrict__ Hh,
                         bf16* __restrict__ Hl, const float* __restrict__ loglam) {
    const int SEG = TT / 128;     // 16
    int b  = blockIdx.x >> 5;
    int cg = blockIdx.x & 31;
    int sx = threadIdx.x;         // 0..7
    int sy = threadIdx.y;         // 0..127
    int s = cg * 8 + sx;
    float lam = 1.0f / (1.0f + expf(-loglam[s]));
    size_t base = ((size_t)(b * TT + sy * SEG)) * SS + s;

    float h = 0.0f;
    #pragma unroll
    for (int i = 0; i < SEG; i++) h = lam * h + Bu[base + (size_t)i * SS];

    __shared__ float carry[128][9];
    __shared__ float cin[128][9];
    carry[sy][sx] = h;
    __syncthreads();
    if (sy == 0) {
        float lamS = lam;
        #pragma unroll
        for (int q = 0; q < 4; q++) lamS *= lamS;     // lam^16
        float c = 0.0f;
        for (int j = 0; j < 128; j++) { cin[j][sx] = c; c = lamS * c + carry[j][sx]; }
    }
    __syncthreads();

    h = cin[sy][sx];
    #pragma unroll
    for (int i = 0; i < SEG; i++) {
        size_t idx = base + (size_t)i * SS;
        h = lam * h + Bu[idx];
        bf16 hb, lb;
        bf_split(h, hb, lb);
        Hh[idx] = hb;
        Hl[idx] = lb;
    }
}

// ---------------- launch ----------------
#define SM_SMALL (1024 + 4 * (192 * 128))   // MT=128, NT=64, NST=4
#define SM_SWIG  (1024 + 2 * (384 * 128))   // MT=128, NT=256, NST=2
#define SM_HEAD  (1024 + 2 * (384 * 128))   // MT=128, NT=256, NST=2

extern "C" void kernel_launch(void* const* d_in, const int* in_sizes, int n_in,
                              void* d_out, int out_size) {
    const int*   x      = (const int*)  d_in[0];
    const float* emb    = (const float*)d_in[1];
    const float* pos    = (const float*)d_in[2];
    const float* loglam = (const float*)d_in[3];
    const float* Bw     = (const float*)d_in[4];
    const float* Cw     = (const float*)d_in[5];
    const float* Dp     = (const float*)d_in[6];
    const float* n1w    = (const float*)d_in[7];
    const float* n1b    = (const float*)d_in[8];
    const float* n2w    = (const float*)d_in[9];
    const float* n2b    = (const float*)d_in[10];
    const float* w1     = (const float*)d_in[11];
    const float* w2     = (const float*)d_in[12];
    const float* w3     = (const float*)d_in[13];
    const float* now    = (const float*)d_in[14];
    const float* nob    = (const float*)d_in[15];
    const float* headW  = (const float*)d_in[16];
    const float* headb  = (const float*)d_in[17];
    float* out = (float*)d_out;

    float *h, *bu;
    bf16 *xnh, *xnl, *buh, *bul, *glh, *gll;
    bf16 *w1h, *w1l, *w2h, *w2l, *w3h, *w3l, *bwh, *bwl, *cwh, *cwl;
    __half *hwh, *hwl;
    cudaGetSymbolAddress((void**)&h,   g_h);
    cudaGetSymbolAddress((void**)&xnh, g_xnh);
    cudaGetSymbolAddress((void**)&xnl, g_xnl);
    cudaGetSymbolAddress((void**)&bu,  g_bu);
    cudaGetSymbolAddress((void**)&buh, g_buh);
    cudaGetSymbolAddress((void**)&bul, g_bul);
    cudaGetSymbolAddress((void**)&glh, g_glh);
    cudaGetSymbolAddress((void**)&gll, g_gll);
    cudaGetSymbolAddress((void**)&w1h, g_w1h);
    cudaGetSymbolAddress((void**)&w1l, g_w1l);
    cudaGetSymbolAddress((void**)&w2h, g_w2h);
    cudaGetSymbolAddress((void**)&w2l, g_w2l);
    cudaGetSymbolAddress((void**)&w3h, g_w3h);
    cudaGetSymbolAddress((void**)&w3l, g_w3l);
    cudaGetSymbolAddress((void**)&bwh, g_bwh);
    cudaGetSymbolAddress((void**)&bwl, g_bwl);
    cudaGetSymbolAddress((void**)&cwh, g_cwh);
    cudaGetSymbolAddress((void**)&cwl, g_cwl);
    cudaGetSymbolAddress((void**)&hwh, g_hwh);
    cudaGetSymbolAddress((void**)&hwl, g_hwl);

    cudaFuncSetAttribute((const void*)gemm3x<128, 64, false, 4, 0, 0>,
                         cudaFuncAttributeMaxDynamicSharedMemorySize, SM_SMALL);
    cudaFuncSetAttribute((const void*)gemm3x<128, 64, false, 4, 0, 1>,
                         cudaFuncAttributeMaxDynamicSharedMemorySize, SM_SMALL);
    cudaFuncSetAttribute((const void*)gemm3x<128, 64, false, 4, 0, 3>,
                         cudaFuncAttributeMaxDynamicSharedMemorySize, SM_SMALL);
    cudaFuncSetAttribute((const void*)gemm3x<128, 256, true, 2, 0, 5>,
                         cudaFuncAttributeMaxDynamicSharedMemorySize, SM_SWIG);
    cudaFuncSetAttribute((const void*)gemm3x<128, 256, false, 2, 1, 4>,
                         cudaFuncAttributeMaxDynamicSharedMemorySize, SM_HEAD);

    // one fused split launch
    {
        long total = (long)VV * DD / 4 + 3L * LLAYERS * DFFN * DD / 4 + 2L * LLAYERS * SS * DD / 4;
        split_all<<<(unsigned)((total + 255) / 256), 256>>>(headW, w1, w2, w3, Bw, Cw);
    }

    embed_k<<<BT, 128>>>(x, emb, pos, h);

    for (int l = 0; l < LLAYERS; l++) {
        ln512<<<BT, 128>>>(h, xnh, xnl, n1w + l * DD, n1b + l * DD, 0);
        // Bu = xn @ Bw^T   [4096,256]
        gemm3x<128, 64, false, 4, 0, 0><<<dim3(32, 4), 256, SM_SMALL>>>(
            xnh, xnl, bwh + (size_t)l * SS * DD, bwl + (size_t)l * SS * DD,
            nullptr, nullptr, bu, nullptr, nullptr, SS, DD, nullptr, nullptr, nullptr);
        ssm_scan<<<64, dim3(8, 128)>>>(bu, buh, bul, loglam + l * SS);
        // h += hscan @ Cw^T + Dp*xn   [4096,512]
        gemm3x<128, 64, false, 4, 0, 1><<<dim3(32, 8), 256, SM_SMALL>>>(
            buh, bul, cwh + (size_t)l * DD * SS, cwl + (size_t)l * DD * SS,
            nullptr, nullptr, h, nullptr, nullptr, DD, SS, Dp + l * DD, xnh, xnl);
        ln512<<<BT, 128>>>(h, xnh, xnl, n2w + l * DD, n2b + l * DD, 0);
        // gl = silu(xn@w1^T)*(xn@w2^T)   [4096,1368]
        gemm3x<128, 256, true, 2, 0, 5><<<dim3(32, 11), 256, SM_SWIG>>>(
            xnh, xnl, w1h + (size_t)l * DFFN * DD, w1l + (size_t)l * DFFN * DD,
            w2h + (size_t)l * DFFN * DD, w2l + (size_t)l * DFFN * DD,
            nullptr, glh, gll, DFFN, DD, nullptr, nullptr, nullptr);
        // h += gl @ w3^T   [4096,512]
        gemm3x<128, 64, false, 4, 0, 3><<<dim3(32, 8), 256, SM_SMALL>>>(
            glh, gll, w3h + (size_t)l * DD * DFFN, w3l + (size_t)l * DD * DFFN,
            nullptr, nullptr, h, nullptr, nullptr, DD, DFFN, nullptr, nullptr, nullptr);
    }

    // final LN -> fp16 hi/lo (head path)
    ln512<<<BT, 128>>>(h, xnh, xnl, now, nob, 1);
    // logits = xn @ headW^T + headb   [4096,32000]  — fp16 2-term, evict-first stores
    gemm3x<128, 256, false, 2, 1, 4><<<dim3(32, 125), 256, SM_HEAD>>>(
        xnh, xnl, (bf16*)hwh, (bf16*)hwl, nullptr, nullptr, out, nullptr, nullptr,
        VV, DD, headb, nullptr, nullptr);
}